// round 2
// baseline (speedup 1.0000x reference)
#include <cuda_runtime.h>
#include <cstdint>

#define D 512
#define BM 128
#define BN 128
#define BK 16
#define KDIM 512

static const int MAX_NODES = 50000;

__device__ float g_h1[(size_t)MAX_NODES * D];
__device__ float g_h2[(size_t)MAX_NODES * D];
__device__ float g_agg[(size_t)MAX_NODES * D];

// ---------------------------------------------------------------------------
// Edge scatter: agg[dst[e]] += h[src[e]]  (one float4 lane-task per thread)
// ---------------------------------------------------------------------------
__global__ void scatter_kernel(const float* __restrict__ h,
                               const int* __restrict__ src,
                               const int* __restrict__ dst,
                               float* __restrict__ agg, int n_edges)
{
    long g = (long)blockIdx.x * blockDim.x + threadIdx.x;
    long total = (long)n_edges * (D / 4);
    if (g >= total) return;
    int e = (int)(g >> 7);          // D/4 == 128
    int c = (int)(g & 127);
    int s = __ldg(src + e);
    int d = __ldg(dst + e);
    float4 v = __ldg(reinterpret_cast<const float4*>(h) + (long)s * (D / 4) + c);
    float* p = agg + (long)d * D + c * 4;
    atomicAdd(p + 0, v.x);
    atomicAdd(p + 1, v.y);
    atomicAdd(p + 2, v.z);
    atomicAdd(p + 3, v.w);
}

// ---------------------------------------------------------------------------
// tf32 helpers
// ---------------------------------------------------------------------------
__device__ __forceinline__ uint32_t f2tf(float x)
{
    uint32_t r;
    asm("cvt.rna.tf32.f32 %0, %1;" : "=r"(r) : "f"(x));
    return r;
}

__device__ __forceinline__ void mma8(float* c, const uint32_t* a, uint32_t b0, uint32_t b1)
{
    asm volatile(
        "mma.sync.aligned.m16n8k8.row.col.f32.tf32.tf32.f32 "
        "{%0,%1,%2,%3}, {%4,%5,%6,%7}, {%8,%9}, {%0,%1,%2,%3};\n"
        : "+f"(c[0]), "+f"(c[1]), "+f"(c[2]), "+f"(c[3])
        : "r"(a[0]), "r"(a[1]), "r"(a[2]), "r"(a[3]), "r"(b0), "r"(b1));
}

// ---------------------------------------------------------------------------
// Fused GEMM:  C = act( (A1 [+ A2]) @ B + bias ),  A row-major [M,KDIM],
// B row-major [KDIM,N] (N % 4 == 0), C row-major [M,N].
// Block tile 128x128, BK=16, 8 warps (4x2), warp tile 32x64, tf32 mma.
// ---------------------------------------------------------------------------
template<bool RELU>
__global__ __launch_bounds__(256)
void gin_gemm(const float* __restrict__ A1, const float* __restrict__ A2,
              const float* __restrict__ B, const float* __restrict__ bias,
              float* __restrict__ Cout, int M, int N)
{
    __shared__ float As[2][BK][BM + 4];   // transposed: As[k][m]
    __shared__ float Bs[2][BK][BN + 4];   // Bs[k][n]

    const int tid  = threadIdx.x;
    const int wid  = tid >> 5;
    const int lane = tid & 31;
    const int wm   = wid & 3;        // 4 warps along M (32 rows each)
    const int wn   = wid >> 2;       // 2 warps along N (64 cols each)
    const int grp  = lane >> 2;      // groupID
    const int tig  = lane & 3;       // thread-in-group

    const int m0 = blockIdx.x * BM;
    const int n0 = blockIdx.y * BN;

    float acc[2][8][4];
#pragma unroll
    for (int mi = 0; mi < 2; mi++)
#pragma unroll
        for (int ni = 0; ni < 8; ni++)
#pragma unroll
            for (int j = 0; j < 4; j++) acc[mi][ni][j] = 0.f;

    const int arow = tid >> 2;         // 0..63  (two passes: +0, +64)
    const int acol = (tid & 3) << 2;   // 0,4,8,12
    const int brow = tid >> 5;         // 0..7   (two passes: +0, +8)
    const int bcol = (tid & 31) << 2;  // 0..124

    float4 aReg[2];
    float4 bReg[2];

    auto fetch = [&](int k0) {
#pragma unroll
        for (int i = 0; i < 2; i++) {
            int gr = m0 + arow + i * 64;
            if (gr < M) {
                float4 v = __ldg(reinterpret_cast<const float4*>(
                    A1 + (size_t)gr * KDIM + k0 + acol));
                if (A2) {
                    float4 w = __ldg(reinterpret_cast<const float4*>(
                        A2 + (size_t)gr * KDIM + k0 + acol));
                    v.x += w.x; v.y += w.y; v.z += w.z; v.w += w.w;
                }
                aReg[i] = v;
            } else {
                aReg[i] = make_float4(0.f, 0.f, 0.f, 0.f);
            }
        }
        int gc = n0 + bcol;
#pragma unroll
        for (int i = 0; i < 2; i++) {
            int gk = k0 + brow + i * 8;      // always < KDIM
            if (gc < N) {
                bReg[i] = __ldg(reinterpret_cast<const float4*>(
                    B + (size_t)gk * N + gc));
            } else {
                bReg[i] = make_float4(0.f, 0.f, 0.f, 0.f);
            }
        }
    };

    auto stage = [&](int buf) {
#pragma unroll
        for (int i = 0; i < 2; i++) {
            int r = arow + i * 64;
            As[buf][acol + 0][r] = __uint_as_float(f2tf(aReg[i].x));
            As[buf][acol + 1][r] = __uint_as_float(f2tf(aReg[i].y));
            As[buf][acol + 2][r] = __uint_as_float(f2tf(aReg[i].z));
            As[buf][acol + 3][r] = __uint_as_float(f2tf(aReg[i].w));
        }
#pragma unroll
        for (int i = 0; i < 2; i++) {
            int r = brow + i * 8;
            float4 t;
            t.x = __uint_as_float(f2tf(bReg[i].x));
            t.y = __uint_as_float(f2tf(bReg[i].y));
            t.z = __uint_as_float(f2tf(bReg[i].z));
            t.w = __uint_as_float(f2tf(bReg[i].w));
            *reinterpret_cast<float4*>(&Bs[buf][r][bcol]) = t;
        }
    };

    fetch(0);
    stage(0);
    __syncthreads();

    const int KT = KDIM / BK;   // 32
    for (int kt = 0; kt < KT; ++kt) {
        const int cur = kt & 1;
        if (kt + 1 < KT) fetch((kt + 1) * BK);

#pragma unroll
        for (int kk = 0; kk < BK; kk += 8) {
            uint32_t af[2][4];
#pragma unroll
            for (int mi = 0; mi < 2; mi++) {
                int r0 = wm * 32 + mi * 16 + grp;
                af[mi][0] = __float_as_uint(As[cur][kk + tig][r0]);
                af[mi][1] = __float_as_uint(As[cur][kk + tig][r0 + 8]);
                af[mi][2] = __float_as_uint(As[cur][kk + tig + 4][r0]);
                af[mi][3] = __float_as_uint(As[cur][kk + tig + 4][r0 + 8]);
            }
#pragma unroll
            for (int ni = 0; ni < 8; ni++) {
                int cn = wn * 64 + ni * 8 + grp;
                uint32_t b0 = __float_as_uint(Bs[cur][kk + tig][cn]);
                uint32_t b1 = __float_as_uint(Bs[cur][kk + tig + 4][cn]);
                mma8(acc[0][ni], af[0], b0, b1);
                mma8(acc[1][ni], af[1], b0, b1);
            }
        }
        if (kt + 1 < KT) stage(cur ^ 1);
        __syncthreads();
    }

    // Epilogue: bias (+relu), float2 stores
#pragma unroll
    for (int ni = 0; ni < 8; ni++) {
        int col = n0 + wn * 64 + ni * 8 + tig * 2;
        if (col >= N) continue;
        float bv0 = bias[col];
        float bv1 = bias[col + 1];
#pragma unroll
        for (int mi = 0; mi < 2; mi++) {
            int rbase = m0 + wm * 32 + mi * 16 + grp;
#pragma unroll
            for (int h = 0; h < 2; h++) {
                int r = rbase + h * 8;
                if (r >= M) continue;
                float x0 = acc[mi][ni][h * 2 + 0] + bv0;
                float x1 = acc[mi][ni][h * 2 + 1] + bv1;
                if (RELU) { x0 = fmaxf(x0, 0.f); x1 = fmaxf(x1, 0.f); }
                float2 o; o.x = x0; o.y = x1;
                *reinterpret_cast<float2*>(Cout + (size_t)r * N + col) = o;
            }
        }
    }
}

// ---------------------------------------------------------------------------
// Launch: 3 x (memset agg, scatter, fused gemm+relu) + classifier gemm
// ---------------------------------------------------------------------------
extern "C" void kernel_launch(void* const* d_in, const int* in_sizes, int n_in,
                              void* d_out, int out_size)
{
    const float* feat = (const float*)d_in[0];
    const int*   src  = (const int*)d_in[1];
    const int*   dst  = (const int*)d_in[2];
    const float* W0   = (const float*)d_in[3];
    const float* b0   = (const float*)d_in[4];
    const float* W1   = (const float*)d_in[5];
    const float* b1   = (const float*)d_in[6];
    const float* W2   = (const float*)d_in[7];
    const float* b2   = (const float*)d_in[8];
    const float* Wc   = (const float*)d_in[9];
    const float* bc   = (const float*)d_in[10];

    const int n_nodes = in_sizes[0] / D;
    const int n_edges = in_sizes[1];
    const int n_cls   = in_sizes[10];

    float *h1, *h2, *agg;
    cudaGetSymbolAddress((void**)&h1, g_h1);
    cudaGetSymbolAddress((void**)&h2, g_h2);
    cudaGetSymbolAddress((void**)&agg, g_agg);

    const size_t aggBytes = (size_t)n_nodes * D * sizeof(float);
    const long   tasks    = (long)n_edges * (D / 4);
    const int    sBlocks  = (int)((tasks + 255) / 256);

    dim3 gGrid((n_nodes + BM - 1) / BM, (D + BN - 1) / BN);
    dim3 cGrid((n_nodes + BM - 1) / BM, (n_cls + BN - 1) / BN);

    // Layer 0
    cudaMemsetAsync(agg, 0, aggBytes);
    scatter_kernel<<<sBlocks, 256>>>(feat, src, dst, agg, n_edges);
    gin_gemm<true><<<gGrid, 256>>>(feat, agg, W0, b0, h1, n_nodes, D);

    // Layer 1
    cudaMemsetAsync(agg, 0, aggBytes);
    scatter_kernel<<<sBlocks, 256>>>(h1, src, dst, agg, n_edges);
    gin_gemm<true><<<gGrid, 256>>>(h1, agg, W1, b1, h2, n_nodes, D);

    // Layer 2
    cudaMemsetAsync(agg, 0, aggBytes);
    scatter_kernel<<<sBlocks, 256>>>(h2, src, dst, agg, n_edges);
    gin_gemm<true><<<gGrid, 256>>>(h2, agg, W2, b2, h1, n_nodes, D);

    // Classifier (no aggregation, no relu)
    gin_gemm<false><<<cGrid, 256>>>(h1, nullptr, Wc, bc, (float*)d_out,
                                    n_nodes, n_cls);
}

// round 3
// speedup vs baseline: 2.4495x; 2.4495x over previous
#include <cuda_runtime.h>
#include <cstdint>

#define D 512
#define D4 128
#define BM 128
#define BN 128
#define BK 16
#define KDIM 512

static const int MAX_NODES = 50000;
static const int MAX_EDGES = 400000;

__device__ float g_h1[(size_t)MAX_NODES * D];
__device__ float g_h2[(size_t)MAX_NODES * D];
__device__ float g_agg[(size_t)MAX_NODES * D];

__device__ int g_deg[MAX_NODES];
__device__ int g_indptr[MAX_NODES + 1];
__device__ int g_cursor[MAX_NODES];
__device__ int g_csr[MAX_EDGES];

// ---------------------------------------------------------------------------
// CSR build: histogram by dst, scan, fill with src ids
// ---------------------------------------------------------------------------
__global__ void hist_kernel(const int* __restrict__ dst, int* __restrict__ deg,
                            int n_edges)
{
    int e = blockIdx.x * blockDim.x + threadIdx.x;
    if (e < n_edges) atomicAdd(&deg[__ldg(dst + e)], 1);
}

__global__ void scan_kernel(const int* __restrict__ deg, int* __restrict__ indptr,
                            int n)
{
    const int T = 1024;
    __shared__ int sh[T];
    int t = threadIdx.x;
    int chunk = (n + T - 1) / T;
    int beg = t * chunk;
    int end = min(beg + chunk, n);
    int s = 0;
    for (int i = beg; i < end; i++) s += deg[i];
    sh[t] = s;
    __syncthreads();
    // Hillis-Steele inclusive scan
    for (int off = 1; off < T; off <<= 1) {
        int v = sh[t];
        int u = (t >= off) ? sh[t - off] : 0;
        __syncthreads();
        sh[t] = v + u;
        __syncthreads();
    }
    int run = (t == 0) ? 0 : sh[t - 1];
    for (int i = beg; i < end; i++) { indptr[i] = run; run += deg[i]; }
    if (t == T - 1) indptr[n] = sh[T - 1];
}

__global__ void fill_kernel(const int* __restrict__ src, const int* __restrict__ dst,
                            const int* __restrict__ indptr, int* __restrict__ cursor,
                            int* __restrict__ csr, int n_edges)
{
    int e = blockIdx.x * blockDim.x + threadIdx.x;
    if (e >= n_edges) return;
    int d = __ldg(dst + e);
    int pos = __ldg(indptr + d) + atomicAdd(&cursor[d], 1);
    csr[pos] = __ldg(src + e);
}

// ---------------------------------------------------------------------------
// Gather aggregation: out[i] = h[i] + sum_{j in N_in(i)} h[j]
// one block (128 threads) per node, float4 per thread, coalesced rows
// ---------------------------------------------------------------------------
__global__ __launch_bounds__(128)
void gather_agg(const float4* __restrict__ h, const int* __restrict__ indptr,
                const int* __restrict__ csr, float4* __restrict__ out)
{
    __shared__ int nb[128];
    const int node = blockIdx.x;
    const int t = threadIdx.x;
    float4 acc = __ldg(h + (size_t)node * D4 + t);    // self term
    const int beg = __ldg(indptr + node);
    const int end = __ldg(indptr + node + 1);
    for (int base = beg; base < end; base += 128) {
        int cnt = min(128, end - base);
        if (t < cnt) nb[t] = __ldg(csr + base + t);
        __syncthreads();
        int i = 0;
        for (; i + 4 <= cnt; i += 4) {
            float4 v0 = __ldg(h + (size_t)nb[i + 0] * D4 + t);
            float4 v1 = __ldg(h + (size_t)nb[i + 1] * D4 + t);
            float4 v2 = __ldg(h + (size_t)nb[i + 2] * D4 + t);
            float4 v3 = __ldg(h + (size_t)nb[i + 3] * D4 + t);
            acc.x += v0.x + v1.x + v2.x + v3.x;
            acc.y += v0.y + v1.y + v2.y + v3.y;
            acc.z += v0.z + v1.z + v2.z + v3.z;
            acc.w += v0.w + v1.w + v2.w + v3.w;
        }
        for (; i < cnt; i++) {
            float4 v = __ldg(h + (size_t)nb[i] * D4 + t);
            acc.x += v.x; acc.y += v.y; acc.z += v.z; acc.w += v.w;
        }
        __syncthreads();
    }
    out[(size_t)node * D4 + t] = acc;
}

// ---------------------------------------------------------------------------
// tf32 helpers
// ---------------------------------------------------------------------------
__device__ __forceinline__ uint32_t f2tf(float x)
{
    uint32_t r;
    asm("cvt.rna.tf32.f32 %0, %1;" : "=r"(r) : "f"(x));
    return r;
}

__device__ __forceinline__ void mma8(float* c, const uint32_t* a, uint32_t b0, uint32_t b1)
{
    asm volatile(
        "mma.sync.aligned.m16n8k8.row.col.f32.tf32.tf32.f32 "
        "{%0,%1,%2,%3}, {%4,%5,%6,%7}, {%8,%9}, {%0,%1,%2,%3};\n"
        : "+f"(c[0]), "+f"(c[1]), "+f"(c[2]), "+f"(c[3])
        : "r"(a[0]), "r"(a[1]), "r"(a[2]), "r"(a[3]), "r"(b0), "r"(b1));
}

// ---------------------------------------------------------------------------
// GEMM: C = act(A @ B + bias), A row-major [M,KDIM], B row-major [KDIM,N]
// Block tile 128x128, BK=16, 8 warps (4x2), warp tile 32x64, tf32 mma.
// ---------------------------------------------------------------------------
template<bool RELU>
__global__ __launch_bounds__(256)
void gin_gemm(const float* __restrict__ A, const float* __restrict__ B,
              const float* __restrict__ bias, float* __restrict__ Cout,
              int M, int N)
{
    __shared__ float As[2][BK][BM + 4];   // transposed: As[k][m]
    __shared__ float Bs[2][BK][BN + 4];   // Bs[k][n]

    const int tid  = threadIdx.x;
    const int wid  = tid >> 5;
    const int lane = tid & 31;
    const int wm   = wid & 3;
    const int wn   = wid >> 2;
    const int grp  = lane >> 2;
    const int tig  = lane & 3;

    const int m0 = blockIdx.x * BM;
    const int n0 = blockIdx.y * BN;

    float acc[2][8][4];
#pragma unroll
    for (int mi = 0; mi < 2; mi++)
#pragma unroll
        for (int ni = 0; ni < 8; ni++)
#pragma unroll
            for (int j = 0; j < 4; j++) acc[mi][ni][j] = 0.f;

    const int arow = tid >> 2;
    const int acol = (tid & 3) << 2;
    const int brow = tid >> 5;
    const int bcol = (tid & 31) << 2;

    float4 aReg[2];
    float4 bReg[2];

    auto fetch = [&](int k0) {
#pragma unroll
        for (int i = 0; i < 2; i++) {
            int gr = m0 + arow + i * 64;
            aReg[i] = (gr < M)
                ? __ldg(reinterpret_cast<const float4*>(A + (size_t)gr * KDIM + k0 + acol))
                : make_float4(0.f, 0.f, 0.f, 0.f);
        }
        int gc = n0 + bcol;
#pragma unroll
        for (int i = 0; i < 2; i++) {
            int gk = k0 + brow + i * 8;
            bReg[i] = (gc < N)
                ? __ldg(reinterpret_cast<const float4*>(B + (size_t)gk * N + gc))
                : make_float4(0.f, 0.f, 0.f, 0.f);
        }
    };

    auto stage = [&](int buf) {
#pragma unroll
        for (int i = 0; i < 2; i++) {
            int r = arow + i * 64;
            As[buf][acol + 0][r] = __uint_as_float(f2tf(aReg[i].x));
            As[buf][acol + 1][r] = __uint_as_float(f2tf(aReg[i].y));
            As[buf][acol + 2][r] = __uint_as_float(f2tf(aReg[i].z));
            As[buf][acol + 3][r] = __uint_as_float(f2tf(aReg[i].w));
        }
#pragma unroll
        for (int i = 0; i < 2; i++) {
            int r = brow + i * 8;
            float4 t;
            t.x = __uint_as_float(f2tf(bReg[i].x));
            t.y = __uint_as_float(f2tf(bReg[i].y));
            t.z = __uint_as_float(f2tf(bReg[i].z));
            t.w = __uint_as_float(f2tf(bReg[i].w));
            *reinterpret_cast<float4*>(&Bs[buf][r][bcol]) = t;
        }
    };

    fetch(0);
    stage(0);
    __syncthreads();

    const int KT = KDIM / BK;
    for (int kt = 0; kt < KT; ++kt) {
        const int cur = kt & 1;
        if (kt + 1 < KT) fetch((kt + 1) * BK);

#pragma unroll
        for (int kk = 0; kk < BK; kk += 8) {
            uint32_t af[2][4];
#pragma unroll
            for (int mi = 0; mi < 2; mi++) {
                int r0 = wm * 32 + mi * 16 + grp;
                af[mi][0] = __float_as_uint(As[cur][kk + tig][r0]);
                af[mi][1] = __float_as_uint(As[cur][kk + tig][r0 + 8]);
                af[mi][2] = __float_as_uint(As[cur][kk + tig + 4][r0]);
                af[mi][3] = __float_as_uint(As[cur][kk + tig + 4][r0 + 8]);
            }
#pragma unroll
            for (int ni = 0; ni < 8; ni++) {
                int cn = wn * 64 + ni * 8 + grp;
                uint32_t b0 = __float_as_uint(Bs[cur][kk + tig][cn]);
                uint32_t b1 = __float_as_uint(Bs[cur][kk + tig + 4][cn]);
                mma8(acc[0][ni], af[0], b0, b1);
                mma8(acc[1][ni], af[1], b0, b1);
            }
        }
        if (kt + 1 < KT) stage(cur ^ 1);
        __syncthreads();
    }

#pragma unroll
    for (int ni = 0; ni < 8; ni++) {
        int col = n0 + wn * 64 + ni * 8 + tig * 2;
        if (col >= N) continue;
        float bv0 = bias[col];
        float bv1 = bias[col + 1];
#pragma unroll
        for (int mi = 0; mi < 2; mi++) {
            int rbase = m0 + wm * 32 + mi * 16 + grp;
#pragma unroll
            for (int h = 0; h < 2; h++) {
                int r = rbase + h * 8;
                if (r >= M) continue;
                float x0 = acc[mi][ni][h * 2 + 0] + bv0;
                float x1 = acc[mi][ni][h * 2 + 1] + bv1;
                if (RELU) { x0 = fmaxf(x0, 0.f); x1 = fmaxf(x1, 0.f); }
                float2 o; o.x = x0; o.y = x1;
                *reinterpret_cast<float2*>(Cout + (size_t)r * N + col) = o;
            }
        }
    }
}

// ---------------------------------------------------------------------------
// Launch
// ---------------------------------------------------------------------------
extern "C" void kernel_launch(void* const* d_in, const int* in_sizes, int n_in,
                              void* d_out, int out_size)
{
    const float* feat = (const float*)d_in[0];
    const int*   src  = (const int*)d_in[1];
    const int*   dst  = (const int*)d_in[2];
    const float* W0   = (const float*)d_in[3];
    const float* b0   = (const float*)d_in[4];
    const float* W1   = (const float*)d_in[5];
    const float* b1   = (const float*)d_in[6];
    const float* W2   = (const float*)d_in[7];
    const float* b2   = (const float*)d_in[8];
    const float* Wc   = (const float*)d_in[9];
    const float* bc   = (const float*)d_in[10];

    const int n_nodes = in_sizes[0] / D;
    const int n_edges = in_sizes[1];
    const int n_cls   = in_sizes[10];

    float *h1, *h2, *agg;
    int *deg, *indptr, *cursor, *csr;
    cudaGetSymbolAddress((void**)&h1, g_h1);
    cudaGetSymbolAddress((void**)&h2, g_h2);
    cudaGetSymbolAddress((void**)&agg, g_agg);
    cudaGetSymbolAddress((void**)&deg, g_deg);
    cudaGetSymbolAddress((void**)&indptr, g_indptr);
    cudaGetSymbolAddress((void**)&cursor, g_cursor);
    cudaGetSymbolAddress((void**)&csr, g_csr);

    const int eBlocks = (n_edges + 255) / 256;

    // ---- CSR build (graph is identical for all 3 layers) ----
    cudaMemsetAsync(deg, 0, (size_t)n_nodes * sizeof(int));
    cudaMemsetAsync(cursor, 0, (size_t)n_nodes * sizeof(int));
    hist_kernel<<<eBlocks, 256>>>(dst, deg, n_edges);
    scan_kernel<<<1, 1024>>>(deg, indptr, n_nodes);
    fill_kernel<<<eBlocks, 256>>>(src, dst, indptr, cursor, csr, n_edges);

    dim3 gGrid((n_nodes + BM - 1) / BM, (D + BN - 1) / BN);
    dim3 cGrid((n_nodes + BM - 1) / BM, (n_cls + BN - 1) / BN);

    // Layer 0
    gather_agg<<<n_nodes, 128>>>((const float4*)feat, indptr, csr, (float4*)agg);
    gin_gemm<true><<<gGrid, 256>>>(agg, W0, b0, h1, n_nodes, D);

    // Layer 1
    gather_agg<<<n_nodes, 128>>>((const float4*)h1, indptr, csr, (float4*)agg);
    gin_gemm<true><<<gGrid, 256>>>(agg, W1, b1, h2, n_nodes, D);

    // Layer 2
    gather_agg<<<n_nodes, 128>>>((const float4*)h2, indptr, csr, (float4*)agg);
    gin_gemm<true><<<gGrid, 256>>>(agg, W2, b2, h1, n_nodes, D);

    // Classifier
    gin_gemm<false><<<cGrid, 256>>>(h1, Wc, bc, (float*)d_out, n_nodes, n_cls);
}

// round 4
// speedup vs baseline: 2.4505x; 1.0004x over previous
#include <cuda_runtime.h>
#include <cstdint>

#define D 512
#define D4 128
#define BM 128
#define BN 128
#define BK 16
#define KDIM 512

static const int MAX_NODES = 50000;
static const int MAX_EDGES = 400000;

__device__ float g_h1[(size_t)MAX_NODES * D];
__device__ float g_h2[(size_t)MAX_NODES * D];
__device__ float g_agg[(size_t)MAX_NODES * D];

__device__ int g_deg[MAX_NODES];
__device__ int g_indptr[MAX_NODES + 1];
__device__ int g_cursor[MAX_NODES];
__device__ int g_csr[MAX_EDGES];

// ---------------------------------------------------------------------------
// CSR build: histogram by dst, scan, fill with src ids
// ---------------------------------------------------------------------------
__global__ void hist_kernel(const int* __restrict__ dst, int* __restrict__ deg,
                            int n_edges)
{
    int e = blockIdx.x * blockDim.x + threadIdx.x;
    if (e < n_edges) atomicAdd(&deg[__ldg(dst + e)], 1);
}

__global__ void scan_kernel(const int* __restrict__ deg, int* __restrict__ indptr,
                            int n)
{
    const int T = 1024;
    __shared__ int sh[T];
    int t = threadIdx.x;
    int chunk = (n + T - 1) / T;
    int beg = t * chunk;
    int end = min(beg + chunk, n);
    int s = 0;
    for (int i = beg; i < end; i++) s += deg[i];
    sh[t] = s;
    __syncthreads();
    // Hillis-Steele inclusive scan
    for (int off = 1; off < T; off <<= 1) {
        int v = sh[t];
        int u = (t >= off) ? sh[t - off] : 0;
        __syncthreads();
        sh[t] = v + u;
        __syncthreads();
    }
    int run = (t == 0) ? 0 : sh[t - 1];
    for (int i = beg; i < end; i++) { indptr[i] = run; run += deg[i]; }
    if (t == T - 1) indptr[n] = sh[T - 1];
}

__global__ void fill_kernel(const int* __restrict__ src, const int* __restrict__ dst,
                            const int* __restrict__ indptr, int* __restrict__ cursor,
                            int* __restrict__ csr, int n_edges)
{
    int e = blockIdx.x * blockDim.x + threadIdx.x;
    if (e >= n_edges) return;
    int d = __ldg(dst + e);
    int pos = __ldg(indptr + d) + atomicAdd(&cursor[d], 1);
    csr[pos] = __ldg(src + e);
}

// ---------------------------------------------------------------------------
// Gather aggregation: out[i] = h[i] + sum_{j in N_in(i)} h[j]
// one block (128 threads) per node, float4 per thread, coalesced rows
// ---------------------------------------------------------------------------
__global__ __launch_bounds__(128)
void gather_agg(const float4* __restrict__ h, const int* __restrict__ indptr,
                const int* __restrict__ csr, float4* __restrict__ out)
{
    __shared__ int nb[128];
    const int node = blockIdx.x;
    const int t = threadIdx.x;
    float4 acc = __ldg(h + (size_t)node * D4 + t);    // self term
    const int beg = __ldg(indptr + node);
    const int end = __ldg(indptr + node + 1);
    for (int base = beg; base < end; base += 128) {
        int cnt = min(128, end - base);
        if (t < cnt) nb[t] = __ldg(csr + base + t);
        __syncthreads();
        int i = 0;
        for (; i + 4 <= cnt; i += 4) {
            float4 v0 = __ldg(h + (size_t)nb[i + 0] * D4 + t);
            float4 v1 = __ldg(h + (size_t)nb[i + 1] * D4 + t);
            float4 v2 = __ldg(h + (size_t)nb[i + 2] * D4 + t);
            float4 v3 = __ldg(h + (size_t)nb[i + 3] * D4 + t);
            acc.x += v0.x + v1.x + v2.x + v3.x;
            acc.y += v0.y + v1.y + v2.y + v3.y;
            acc.z += v0.z + v1.z + v2.z + v3.z;
            acc.w += v0.w + v1.w + v2.w + v3.w;
        }
        for (; i < cnt; i++) {
            float4 v = __ldg(h + (size_t)nb[i] * D4 + t);
            acc.x += v.x; acc.y += v.y; acc.z += v.z; acc.w += v.w;
        }
        __syncthreads();
    }
    out[(size_t)node * D4 + t] = acc;
}

// ---------------------------------------------------------------------------
// tf32 helpers
// ---------------------------------------------------------------------------
__device__ __forceinline__ uint32_t f2tf(float x)
{
    uint32_t r;
    asm("cvt.rna.tf32.f32 %0, %1;" : "=r"(r) : "f"(x));
    return r;
}

__device__ __forceinline__ void mma8(float* c, const uint32_t* a, uint32_t b0, uint32_t b1)
{
    asm volatile(
        "mma.sync.aligned.m16n8k8.row.col.f32.tf32.tf32.f32 "
        "{%0,%1,%2,%3}, {%4,%5,%6,%7}, {%8,%9}, {%0,%1,%2,%3};\n"
        : "+f"(c[0]), "+f"(c[1]), "+f"(c[2]), "+f"(c[3])
        : "r"(a[0]), "r"(a[1]), "r"(a[2]), "r"(a[3]), "r"(b0), "r"(b1));
}

// ---------------------------------------------------------------------------
// GEMM: C = act(A @ B + bias), A row-major [M,KDIM], B row-major [KDIM,N]
// Block tile 128x128, BK=16, 8 warps (4x2), warp tile 32x64, tf32 mma.
// ---------------------------------------------------------------------------
template<bool RELU>
__global__ __launch_bounds__(256)
void gin_gemm(const float* __restrict__ A, const float* __restrict__ B,
              const float* __restrict__ bias, float* __restrict__ Cout,
              int M, int N)
{
    __shared__ float As[2][BK][BM + 4];   // transposed: As[k][m]
    __shared__ float Bs[2][BK][BN + 4];   // Bs[k][n]

    const int tid  = threadIdx.x;
    const int wid  = tid >> 5;
    const int lane = tid & 31;
    const int wm   = wid & 3;
    const int wn   = wid >> 2;
    const int grp  = lane >> 2;
    const int tig  = lane & 3;

    const int m0 = blockIdx.x * BM;
    const int n0 = blockIdx.y * BN;

    float acc[2][8][4];
#pragma unroll
    for (int mi = 0; mi < 2; mi++)
#pragma unroll
        for (int ni = 0; ni < 8; ni++)
#pragma unroll
            for (int j = 0; j < 4; j++) acc[mi][ni][j] = 0.f;

    const int arow = tid >> 2;
    const int acol = (tid & 3) << 2;
    const int brow = tid >> 5;
    const int bcol = (tid & 31) << 2;

    float4 aReg[2];
    float4 bReg[2];

    auto fetch = [&](int k0) {
#pragma unroll
        for (int i = 0; i < 2; i++) {
            int gr = m0 + arow + i * 64;
            aReg[i] = (gr < M)
                ? __ldg(reinterpret_cast<const float4*>(A + (size_t)gr * KDIM + k0 + acol))
                : make_float4(0.f, 0.f, 0.f, 0.f);
        }
        int gc = n0 + bcol;
#pragma unroll
        for (int i = 0; i < 2; i++) {
            int gk = k0 + brow + i * 8;
            bReg[i] = (gc < N)
                ? __ldg(reinterpret_cast<const float4*>(B + (size_t)gk * N + gc))
                : make_float4(0.f, 0.f, 0.f, 0.f);
        }
    };

    auto stage = [&](int buf) {
#pragma unroll
        for (int i = 0; i < 2; i++) {
            int r = arow + i * 64;
            As[buf][acol + 0][r] = __uint_as_float(f2tf(aReg[i].x));
            As[buf][acol + 1][r] = __uint_as_float(f2tf(aReg[i].y));
            As[buf][acol + 2][r] = __uint_as_float(f2tf(aReg[i].z));
            As[buf][acol + 3][r] = __uint_as_float(f2tf(aReg[i].w));
        }
#pragma unroll
        for (int i = 0; i < 2; i++) {
            int r = brow + i * 8;
            float4 t;
            t.x = __uint_as_float(f2tf(bReg[i].x));
            t.y = __uint_as_float(f2tf(bReg[i].y));
            t.z = __uint_as_float(f2tf(bReg[i].z));
            t.w = __uint_as_float(f2tf(bReg[i].w));
            *reinterpret_cast<float4*>(&Bs[buf][r][bcol]) = t;
        }
    };

    fetch(0);
    stage(0);
    __syncthreads();

    const int KT = KDIM / BK;
    for (int kt = 0; kt < KT; ++kt) {
        const int cur = kt & 1;
        if (kt + 1 < KT) fetch((kt + 1) * BK);

#pragma unroll
        for (int kk = 0; kk < BK; kk += 8) {
            uint32_t af[2][4];
#pragma unroll
            for (int mi = 0; mi < 2; mi++) {
                int r0 = wm * 32 + mi * 16 + grp;
                af[mi][0] = __float_as_uint(As[cur][kk + tig][r0]);
                af[mi][1] = __float_as_uint(As[cur][kk + tig][r0 + 8]);
                af[mi][2] = __float_as_uint(As[cur][kk + tig + 4][r0]);
                af[mi][3] = __float_as_uint(As[cur][kk + tig + 4][r0 + 8]);
            }
#pragma unroll
            for (int ni = 0; ni < 8; ni++) {
                int cn = wn * 64 + ni * 8 + grp;
                uint32_t b0 = __float_as_uint(Bs[cur][kk + tig][cn]);
                uint32_t b1 = __float_as_uint(Bs[cur][kk + tig + 4][cn]);
                mma8(acc[0][ni], af[0], b0, b1);
                mma8(acc[1][ni], af[1], b0, b1);
            }
        }
        if (kt + 1 < KT) stage(cur ^ 1);
        __syncthreads();
    }

#pragma unroll
    for (int ni = 0; ni < 8; ni++) {
        int col = n0 + wn * 64 + ni * 8 + tig * 2;
        if (col >= N) continue;
        float bv0 = bias[col];
        float bv1 = bias[col + 1];
#pragma unroll
        for (int mi = 0; mi < 2; mi++) {
            int rbase = m0 + wm * 32 + mi * 16 + grp;
#pragma unroll
            for (int h = 0; h < 2; h++) {
                int r = rbase + h * 8;
                if (r >= M) continue;
                float x0 = acc[mi][ni][h * 2 + 0] + bv0;
                float x1 = acc[mi][ni][h * 2 + 1] + bv1;
                if (RELU) { x0 = fmaxf(x0, 0.f); x1 = fmaxf(x1, 0.f); }
                float2 o; o.x = x0; o.y = x1;
                *reinterpret_cast<float2*>(Cout + (size_t)r * N + col) = o;
            }
        }
    }
}

// ---------------------------------------------------------------------------
// Launch
// ---------------------------------------------------------------------------
extern "C" void kernel_launch(void* const* d_in, const int* in_sizes, int n_in,
                              void* d_out, int out_size)
{
    const float* feat = (const float*)d_in[0];
    const int*   src  = (const int*)d_in[1];
    const int*   dst  = (const int*)d_in[2];
    const float* W0   = (const float*)d_in[3];
    const float* b0   = (const float*)d_in[4];
    const float* W1   = (const float*)d_in[5];
    const float* b1   = (const float*)d_in[6];
    const float* W2   = (const float*)d_in[7];
    const float* b2   = (const float*)d_in[8];
    const float* Wc   = (const float*)d_in[9];
    const float* bc   = (const float*)d_in[10];

    const int n_nodes = in_sizes[0] / D;
    const int n_edges = in_sizes[1];
    const int n_cls   = in_sizes[10];

    float *h1, *h2, *agg;
    int *deg, *indptr, *cursor, *csr;
    cudaGetSymbolAddress((void**)&h1, g_h1);
    cudaGetSymbolAddress((void**)&h2, g_h2);
    cudaGetSymbolAddress((void**)&agg, g_agg);
    cudaGetSymbolAddress((void**)&deg, g_deg);
    cudaGetSymbolAddress((void**)&indptr, g_indptr);
    cudaGetSymbolAddress((void**)&cursor, g_cursor);
    cudaGetSymbolAddress((void**)&csr, g_csr);

    const int eBlocks = (n_edges + 255) / 256;

    // ---- CSR build (graph is identical for all 3 layers) ----
    cudaMemsetAsync(deg, 0, (size_t)n_nodes * sizeof(int));
    cudaMemsetAsync(cursor, 0, (size_t)n_nodes * sizeof(int));
    hist_kernel<<<eBlocks, 256>>>(dst, deg, n_edges);
    scan_kernel<<<1, 1024>>>(deg, indptr, n_nodes);
    fill_kernel<<<eBlocks, 256>>>(src, dst, indptr, cursor, csr, n_edges);

    dim3 gGrid((n_nodes + BM - 1) / BM, (D + BN - 1) / BN);
    dim3 cGrid((n_nodes + BM - 1) / BM, (n_cls + BN - 1) / BN);

    // Layer 0
    gather_agg<<<n_nodes, 128>>>((const float4*)feat, indptr, csr, (float4*)agg);
    gin_gemm<true><<<gGrid, 256>>>(agg, W0, b0, h1, n_nodes, D);

    // Layer 1
    gather_agg<<<n_nodes, 128>>>((const float4*)h1, indptr, csr, (float4*)agg);
    gin_gemm<true><<<gGrid, 256>>>(agg, W1, b1, h2, n_nodes, D);

    // Layer 2
    gather_agg<<<n_nodes, 128>>>((const float4*)h2, indptr, csr, (float4*)agg);
    gin_gemm<true><<<gGrid, 256>>>(agg, W2, b2, h1, n_nodes, D);

    // Classifier
    gin_gemm<false><<<cGrid, 256>>>(h1, Wc, bc, (float*)d_out, n_nodes, n_cls);
}

// round 6
// speedup vs baseline: 3.1002x; 1.2651x over previous
#include <cuda_runtime.h>
#include <cstdint>

#define D 512
#define D4 128
#define BM 128
#define BN 128
#define KDIM 512

static const int MAX_NODES = 50000;
static const int MAX_EDGES = 400000;

__device__ float g_h1[(size_t)MAX_NODES * D];
__device__ float g_h2[(size_t)MAX_NODES * D];
__device__ float g_agg[(size_t)MAX_NODES * D];

__device__ int g_deg[MAX_NODES];
__device__ int g_indptr[MAX_NODES + 1];
__device__ int g_cursor[MAX_NODES];
__device__ int g_csr[MAX_EDGES];

// ===========================================================================
// helpers
// ===========================================================================
__device__ __forceinline__ uint32_t smem_to_u32(const void* p) {
    uint32_t a;
    asm("{ .reg .u64 t; cvta.to.shared.u64 t, %1; cvt.u32.u64 %0, t; }"
        : "=r"(a) : "l"(p));
    return a;
}

__device__ __forceinline__ uint32_t f2tf(float x)
{
    uint32_t r;
    asm("cvt.rna.tf32.f32 %0, %1;" : "=r"(r) : "f"(x));
    return r;
}

__device__ __forceinline__ void cp16(uint32_t dst, const void* src, int sz)
{
    asm volatile("cp.async.cg.shared.global [%0], [%1], 16, %2;"
                 :: "r"(dst), "l"(src), "r"(sz) : "memory");
}
#define CP_COMMIT() asm volatile("cp.async.commit_group;" ::: "memory")
#define CP_WAIT1()  asm volatile("cp.async.wait_group 1;" ::: "memory")

__device__ __forceinline__ void mma8(float* c, const uint32_t* a, uint32_t b0, uint32_t b1)
{
    asm volatile(
        "mma.sync.aligned.m16n8k8.row.col.f32.tf32.tf32.f32 "
        "{%0,%1,%2,%3}, {%4,%5,%6,%7}, {%8,%9}, {%0,%1,%2,%3};\n"
        : "+f"(c[0]), "+f"(c[1]), "+f"(c[2]), "+f"(c[3])
        : "r"(a[0]), "r"(a[1]), "r"(a[2]), "r"(a[3]), "r"(b0), "r"(b1));
}

// ===========================================================================
// CSR build
// ===========================================================================
__global__ void hist_kernel(const int* __restrict__ dst, int* __restrict__ deg,
                            int n_edges)
{
    int e = blockIdx.x * blockDim.x + threadIdx.x;
    if (e < n_edges) atomicAdd(&deg[__ldg(dst + e)], 1);
}

__global__ void scan_kernel(const int* __restrict__ deg, int* __restrict__ indptr,
                            int n)
{
    const int T = 1024;
    __shared__ int sh[T];
    int t = threadIdx.x;
    int chunk = (n + T - 1) / T;
    int beg = t * chunk;
    int end = min(beg + chunk, n);
    int s = 0;
    for (int i = beg; i < end; i++) s += deg[i];
    sh[t] = s;
    __syncthreads();
    for (int off = 1; off < T; off <<= 1) {
        int v = sh[t];
        int u = (t >= off) ? sh[t - off] : 0;
        __syncthreads();
        sh[t] = v + u;
        __syncthreads();
    }
    int run = (t == 0) ? 0 : sh[t - 1];
    for (int i = beg; i < end; i++) { indptr[i] = run; run += deg[i]; }
    if (t == T - 1) indptr[n] = sh[T - 1];
}

__global__ void fill_kernel(const int* __restrict__ src, const int* __restrict__ dst,
                            const int* __restrict__ indptr, int* __restrict__ cursor,
                            int* __restrict__ csr, int n_edges)
{
    int e = blockIdx.x * blockDim.x + threadIdx.x;
    if (e >= n_edges) return;
    int d = __ldg(dst + e);
    int pos = __ldg(indptr + d) + atomicAdd(&cursor[d], 1);
    csr[pos] = __ldg(src + e);
}

// ===========================================================================
// Gather aggregation: out[i] = h[i] + sum_{j in N_in(i)} h[j]
// ===========================================================================
__global__ __launch_bounds__(128)
void gather_agg(const float4* __restrict__ h, const int* __restrict__ indptr,
                const int* __restrict__ csr, float4* __restrict__ out)
{
    __shared__ int nb[128];
    const int node = blockIdx.x;
    const int t = threadIdx.x;
    float4 acc = __ldg(h + (size_t)node * D4 + t);
    const int beg = __ldg(indptr + node);
    const int end = __ldg(indptr + node + 1);
    for (int base = beg; base < end; base += 128) {
        int cnt = min(128, end - base);
        if (t < cnt) nb[t] = __ldg(csr + base + t);
        __syncthreads();
        int i = 0;
        for (; i + 4 <= cnt; i += 4) {
            float4 v0 = __ldg(h + (size_t)nb[i + 0] * D4 + t);
            float4 v1 = __ldg(h + (size_t)nb[i + 1] * D4 + t);
            float4 v2 = __ldg(h + (size_t)nb[i + 2] * D4 + t);
            float4 v3 = __ldg(h + (size_t)nb[i + 3] * D4 + t);
            acc.x += v0.x + v1.x + v2.x + v3.x;
            acc.y += v0.y + v1.y + v2.y + v3.y;
            acc.z += v0.z + v1.z + v2.z + v3.z;
            acc.w += v0.w + v1.w + v2.w + v3.w;
        }
        for (; i < cnt; i++) {
            float4 v = __ldg(h + (size_t)nb[i] * D4 + t);
            acc.x += v.x; acc.y += v.y; acc.z += v.z; acc.w += v.w;
        }
        __syncthreads();
    }
    out[(size_t)node * D4 + t] = acc;
}

// ===========================================================================
// tf32 mma.sync GEMM, cp.async 3-stage pipeline.
// C[M,N] = act(A[M,512] @ B[512,N] + bias).  Block 128x128, BK=32.
// SMEM per stage: A raw f32 [128][36] (18432B) + B raw f32 [32][136] (17408B).
// tf32 cvt happens at fragment-load time.
// ===========================================================================
#define GBK 32
#define GKT (KDIM / GBK)          // 16
#define A_PITCH 36                // floats
#define B_PITCH 136               // floats
#define AS_BYTES (128 * A_PITCH * 4)          // 18432
#define BS_BYTES (GBK * B_PITCH * 4)          // 17408
#define STAGE_BYTES (AS_BYTES + BS_BYTES)     // 35840
#define GSMEM_TOTAL (3 * STAGE_BYTES)         // 107520

template<bool RELU>
__global__ __launch_bounds__(256, 2)
void gin_gemm(const float* __restrict__ A, const float* __restrict__ B,
              const float* __restrict__ bias, float* __restrict__ Cout,
              int M, int N)
{
    extern __shared__ char smem[];
    const uint32_t sb = smem_to_u32(smem);

    const int tid  = threadIdx.x;
    const int wid  = tid >> 5;
    const int lane = tid & 31;
    const int wm   = wid & 3;
    const int wn   = wid >> 2;
    const int grp  = lane >> 2;
    const int tig  = lane & 3;

    const int m0 = blockIdx.x * BM;
    const int n0 = blockIdx.y * BN;

    float acc[2][8][4];
#pragma unroll
    for (int mi = 0; mi < 2; mi++)
#pragma unroll
        for (int ni = 0; ni < 8; ni++)
#pragma unroll
            for (int j = 0; j < 4; j++) acc[mi][ni][j] = 0.f;

    // ---- async copy of tile kt into stage st ----
    auto issue = [&](int kt, int st) {
        const int kbase = kt * GBK;
        const uint32_t sA = sb + st * STAGE_BYTES;
        const uint32_t sB = sA + AS_BYTES;
        // A: 128 rows x 32 floats = 1024 x 16B chunks / 4 per thread
#pragma unroll
        for (int i = 0; i < 4; i++) {
            int idx = tid + i * 256;
            int row = idx >> 3;
            int u   = idx & 7;
            int gr  = m0 + row;
            bool ok = (gr < M);
            const float* src = ok ? (A + (size_t)gr * KDIM + kbase + u * 4) : A;
            cp16(sA + row * (A_PITCH * 4) + u * 16, src, ok ? 16 : 0);
        }
        // B: 32 k-rows x 128 floats = 1024 x 16B chunks / 4 per thread
#pragma unroll
        for (int i = 0; i < 4; i++) {
            int idx = tid + i * 256;
            int row = idx >> 5;
            int u   = idx & 31;
            int col = n0 + u * 4;
            bool ok = (col + 4 <= N);
            const float* src = ok ? (B + (size_t)(kbase + row) * N + col) : B;
            cp16(sB + row * (B_PITCH * 4) + u * 16, src, ok ? 16 : 0);
        }
    };

    // ---- compute one staged tile ----
    auto compute = [&](int st) {
        const float* As = (const float*)(smem + st * STAGE_BYTES);
        const float* Bs = (const float*)(smem + st * STAGE_BYTES + AS_BYTES);
#pragma unroll
        for (int s = 0; s < 4; s++) {
            const int kk = s * 8;
            uint32_t af[2][4];
#pragma unroll
            for (int mi = 0; mi < 2; mi++) {
                int r0 = wm * 32 + mi * 16 + grp;
                af[mi][0] = f2tf(As[r0 * A_PITCH + kk + tig]);
                af[mi][1] = f2tf(As[(r0 + 8) * A_PITCH + kk + tig]);
                af[mi][2] = f2tf(As[r0 * A_PITCH + kk + tig + 4]);
                af[mi][3] = f2tf(As[(r0 + 8) * A_PITCH + kk + tig + 4]);
            }
#pragma unroll
            for (int h = 0; h < 2; h++) {
                uint32_t bf[4][2];
#pragma unroll
                for (int q = 0; q < 4; q++) {
                    int cn = wn * 64 + (h * 4 + q) * 8 + grp;
                    bf[q][0] = f2tf(Bs[(kk + tig) * B_PITCH + cn]);
                    bf[q][1] = f2tf(Bs[(kk + tig + 4) * B_PITCH + cn]);
                }
#pragma unroll
                for (int q = 0; q < 4; q++) {
                    mma8(acc[0][h * 4 + q], af[0], bf[q][0], bf[q][1]);
                    mma8(acc[1][h * 4 + q], af[1], bf[q][0], bf[q][1]);
                }
            }
        }
    };

    // ---- 3-stage mainloop ----
    issue(0, 0); CP_COMMIT();
    issue(1, 1); CP_COMMIT();
    for (int kt = 0; kt < GKT; kt++) {
        CP_WAIT1();
        __syncthreads();
        const int nx = kt + 2;
        if (nx < GKT) issue(nx, nx % 3);
        CP_COMMIT();
        compute(kt % 3);
    }

    // ---- epilogue ----
#pragma unroll
    for (int ni = 0; ni < 8; ni++) {
        int col = n0 + wn * 64 + ni * 8 + tig * 2;
        if (col >= N) continue;
        float bv0 = __ldg(bias + col);
        float bv1 = __ldg(bias + col + 1);
#pragma unroll
        for (int mi = 0; mi < 2; mi++) {
            int rbase = m0 + wm * 32 + mi * 16 + grp;
#pragma unroll
            for (int h = 0; h < 2; h++) {
                int r = rbase + h * 8;
                if (r >= M) continue;
                float x0 = acc[mi][ni][h * 2 + 0] + bv0;
                float x1 = acc[mi][ni][h * 2 + 1] + bv1;
                if (RELU) { x0 = fmaxf(x0, 0.f); x1 = fmaxf(x1, 0.f); }
                float2 o; o.x = x0; o.y = x1;
                *reinterpret_cast<float2*>(Cout + (size_t)r * N + col) = o;
            }
        }
    }
}

// ===========================================================================
// Launch
// ===========================================================================
extern "C" void kernel_launch(void* const* d_in, const int* in_sizes, int n_in,
                              void* d_out, int out_size)
{
    const float* feat = (const float*)d_in[0];
    const int*   src  = (const int*)d_in[1];
    const int*   dst  = (const int*)d_in[2];
    const float* W0   = (const float*)d_in[3];
    const float* b0   = (const float*)d_in[4];
    const float* W1   = (const float*)d_in[5];
    const float* b1   = (const float*)d_in[6];
    const float* W2   = (const float*)d_in[7];
    const float* b2   = (const float*)d_in[8];
    const float* Wc   = (const float*)d_in[9];
    const float* bc   = (const float*)d_in[10];

    const int n_nodes = in_sizes[0] / D;
    const int n_edges = in_sizes[1];
    const int n_cls   = in_sizes[10];

    float *h1, *h2, *agg;
    int *deg, *indptr, *cursor, *csr;
    cudaGetSymbolAddress((void**)&h1, g_h1);
    cudaGetSymbolAddress((void**)&h2, g_h2);
    cudaGetSymbolAddress((void**)&agg, g_agg);
    cudaGetSymbolAddress((void**)&deg, g_deg);
    cudaGetSymbolAddress((void**)&indptr, g_indptr);
    cudaGetSymbolAddress((void**)&cursor, g_cursor);
    cudaGetSymbolAddress((void**)&csr, g_csr);

    cudaFuncSetAttribute(gin_gemm<true>,
                         cudaFuncAttributeMaxDynamicSharedMemorySize, GSMEM_TOTAL);
    cudaFuncSetAttribute(gin_gemm<false>,
                         cudaFuncAttributeMaxDynamicSharedMemorySize, GSMEM_TOTAL);

    const int eBlocks = (n_edges + 255) / 256;

    // ---- CSR build (graph identical for all 3 layers) ----
    cudaMemsetAsync(deg, 0, (size_t)n_nodes * sizeof(int));
    cudaMemsetAsync(cursor, 0, (size_t)n_nodes * sizeof(int));
    hist_kernel<<<eBlocks, 256>>>(dst, deg, n_edges);
    scan_kernel<<<1, 1024>>>(deg, indptr, n_nodes);
    fill_kernel<<<eBlocks, 256>>>(src, dst, indptr, cursor, csr, n_edges);

    dim3 gGrid((n_nodes + BM - 1) / BM, (D + BN - 1) / BN);
    dim3 cGrid((n_nodes + BM - 1) / BM, (n_cls + BN - 1) / BN);

    // Layer 0
    gather_agg<<<n_nodes, 128>>>((const float4*)feat, indptr, csr, (float4*)agg);
    gin_gemm<true><<<gGrid, 256, GSMEM_TOTAL>>>(agg, W0, b0, h1, n_nodes, D);

    // Layer 1
    gather_agg<<<n_nodes, 128>>>((const float4*)h1, indptr, csr, (float4*)agg);
    gin_gemm<true><<<gGrid, 256, GSMEM_TOTAL>>>(agg, W1, b1, h2, n_nodes, D);

    // Layer 2
    gather_agg<<<n_nodes, 128>>>((const float4*)h2, indptr, csr, (float4*)agg);
    gin_gemm<true><<<gGrid, 256, GSMEM_TOTAL>>>(agg, W2, b2, h1, n_nodes, D);

    // Classifier (no relu)
    gin_gemm<false><<<cGrid, 256, GSMEM_TOTAL>>>(h1, Wc, bc, (float*)d_out,
                                                 n_nodes, n_cls);
}

// round 7
// speedup vs baseline: 3.3627x; 1.0847x over previous
#include <cuda_runtime.h>
#include <cstdint>

#define D 512
#define D4 128
#define BM 128
#define BN 128
#define KDIM 512

static const int MAX_NODES = 50000;
static const int MAX_EDGES = 400000;

__device__ float g_h1[(size_t)MAX_NODES * D];
__device__ float g_h2[(size_t)MAX_NODES * D];
__device__ float g_agg[(size_t)MAX_NODES * D];
__device__ float g_wt[3 * 512 * 512 + 512 * 64];   // tf32-rounded weights

__device__ int g_deg[MAX_NODES];
__device__ int g_indptr[MAX_NODES + 1];
__device__ int g_cursor[MAX_NODES];
__device__ int g_csr[MAX_EDGES];

// ===========================================================================
// helpers
// ===========================================================================
__device__ __forceinline__ uint32_t smem_to_u32(const void* p) {
    uint32_t a;
    asm("{ .reg .u64 t; cvta.to.shared.u64 t, %1; cvt.u32.u64 %0, t; }"
        : "=r"(a) : "l"(p));
    return a;
}

__device__ __forceinline__ uint32_t f2tf(float x)
{
    uint32_t r;
    asm("cvt.rna.tf32.f32 %0, %1;" : "=r"(r) : "f"(x));
    return r;
}

__device__ __forceinline__ void cp16(uint32_t dst, const void* src, int sz)
{
    asm volatile("cp.async.cg.shared.global [%0], [%1], 16, %2;"
                 :: "r"(dst), "l"(src), "r"(sz) : "memory");
}
#define CP_COMMIT() asm volatile("cp.async.commit_group;" ::: "memory")
#define CP_WAIT1()  asm volatile("cp.async.wait_group 1;" ::: "memory")

__device__ __forceinline__ void mma8(float* c, const uint32_t* a, uint32_t b0, uint32_t b1)
{
    asm volatile(
        "mma.sync.aligned.m16n8k8.row.col.f32.tf32.tf32.f32 "
        "{%0,%1,%2,%3}, {%4,%5,%6,%7}, {%8,%9}, {%0,%1,%2,%3};\n"
        : "+f"(c[0]), "+f"(c[1]), "+f"(c[2]), "+f"(c[3])
        : "r"(a[0]), "r"(a[1]), "r"(a[2]), "r"(a[3]), "r"(b0), "r"(b1));
}

// ===========================================================================
// weight pre-conversion to tf32 (rna)
// ===========================================================================
__global__ void cvt_tf32_kernel(const float4* __restrict__ in,
                                float4* __restrict__ out, int n4)
{
    int i = blockIdx.x * blockDim.x + threadIdx.x;
    if (i >= n4) return;
    float4 v = __ldg(in + i);
    float4 t;
    t.x = __uint_as_float(f2tf(v.x));
    t.y = __uint_as_float(f2tf(v.y));
    t.z = __uint_as_float(f2tf(v.z));
    t.w = __uint_as_float(f2tf(v.w));
    out[i] = t;
}

// ===========================================================================
// CSR build
// ===========================================================================
__global__ void hist_kernel(const int* __restrict__ dst, int* __restrict__ deg,
                            int n_edges)
{
    int e = blockIdx.x * blockDim.x + threadIdx.x;
    if (e < n_edges) atomicAdd(&deg[__ldg(dst + e)], 1);
}

__global__ void scan_kernel(const int* __restrict__ deg, int* __restrict__ indptr,
                            int n)
{
    const int T = 1024;
    __shared__ int sh[T];
    int t = threadIdx.x;
    int chunk = (n + T - 1) / T;
    int beg = t * chunk;
    int end = min(beg + chunk, n);
    int s = 0;
    for (int i = beg; i < end; i++) s += deg[i];
    sh[t] = s;
    __syncthreads();
    for (int off = 1; off < T; off <<= 1) {
        int v = sh[t];
        int u = (t >= off) ? sh[t - off] : 0;
        __syncthreads();
        sh[t] = v + u;
        __syncthreads();
    }
    int run = (t == 0) ? 0 : sh[t - 1];
    for (int i = beg; i < end; i++) { indptr[i] = run; run += deg[i]; }
    if (t == T - 1) indptr[n] = sh[T - 1];
}

__global__ void fill_kernel(const int* __restrict__ src, const int* __restrict__ dst,
                            const int* __restrict__ indptr, int* __restrict__ cursor,
                            int* __restrict__ csr, int n_edges)
{
    int e = blockIdx.x * blockDim.x + threadIdx.x;
    if (e >= n_edges) return;
    int d = __ldg(dst + e);
    int pos = __ldg(indptr + d) + atomicAdd(&cursor[d], 1);
    csr[pos] = __ldg(src + e);
}

// ===========================================================================
// Gather aggregation: out[i] = tf32_round( h[i] + sum_{j in N_in(i)} h[j] )
// Streaming store (evict-first) keeps h resident in L2.
// ===========================================================================
__global__ __launch_bounds__(128)
void gather_agg(const float4* __restrict__ h, const int* __restrict__ indptr,
                const int* __restrict__ csr, float4* __restrict__ out)
{
    __shared__ int nb[128];
    const int node = blockIdx.x;
    const int t = threadIdx.x;
    float4 acc = __ldg(h + (size_t)node * D4 + t);
    const int beg = __ldg(indptr + node);
    const int end = __ldg(indptr + node + 1);
    for (int base = beg; base < end; base += 128) {
        int cnt = min(128, end - base);
        if (t < cnt) nb[t] = __ldg(csr + base + t);
        __syncthreads();
        int i = 0;
        for (; i + 4 <= cnt; i += 4) {
            float4 v0 = __ldg(h + (size_t)nb[i + 0] * D4 + t);
            float4 v1 = __ldg(h + (size_t)nb[i + 1] * D4 + t);
            float4 v2 = __ldg(h + (size_t)nb[i + 2] * D4 + t);
            float4 v3 = __ldg(h + (size_t)nb[i + 3] * D4 + t);
            acc.x += v0.x + v1.x + v2.x + v3.x;
            acc.y += v0.y + v1.y + v2.y + v3.y;
            acc.z += v0.z + v1.z + v2.z + v3.z;
            acc.w += v0.w + v1.w + v2.w + v3.w;
        }
        for (; i < cnt; i++) {
            float4 v = __ldg(h + (size_t)nb[i] * D4 + t);
            acc.x += v.x; acc.y += v.y; acc.z += v.z; acc.w += v.w;
        }
        __syncthreads();
    }
    float4 o;
    o.x = __uint_as_float(f2tf(acc.x));
    o.y = __uint_as_float(f2tf(acc.y));
    o.z = __uint_as_float(f2tf(acc.z));
    o.w = __uint_as_float(f2tf(acc.w));
    __stcs(out + (size_t)node * D4 + t, o);
}

// ===========================================================================
// tf32 mma.sync GEMM, cp.async 3-stage pipeline, NO cvt in mainloop
// (A and B are pre-rounded to tf32 by producers).
// C[M,N] = act(A[M,512] @ B[512,N] + bias).  Block 128x128, BK=32.
// ===========================================================================
#define GBK 32
#define GKT (KDIM / GBK)          // 16
#define A_PITCH 36                // floats
#define B_PITCH 136               // floats
#define AS_BYTES (128 * A_PITCH * 4)          // 18432
#define BS_BYTES (GBK * B_PITCH * 4)          // 17408
#define STAGE_BYTES (AS_BYTES + BS_BYTES)     // 35840
#define GSMEM_TOTAL (3 * STAGE_BYTES)         // 107520

template<bool RELU, bool ROUND>
__global__ __launch_bounds__(256, 2)
void gin_gemm(const float* __restrict__ A, const float* __restrict__ B,
              const float* __restrict__ bias, float* __restrict__ Cout,
              int M, int N)
{
    extern __shared__ char smem[];
    const uint32_t sb = smem_to_u32(smem);

    const int tid  = threadIdx.x;
    const int wid  = tid >> 5;
    const int lane = tid & 31;
    const int wm   = wid & 3;
    const int wn   = wid >> 2;
    const int grp  = lane >> 2;
    const int tig  = lane & 3;

    const int m0 = blockIdx.x * BM;
    const int n0 = blockIdx.y * BN;

    float acc[2][8][4];
#pragma unroll
    for (int mi = 0; mi < 2; mi++)
#pragma unroll
        for (int ni = 0; ni < 8; ni++)
#pragma unroll
            for (int j = 0; j < 4; j++) acc[mi][ni][j] = 0.f;

    auto issue = [&](int kt, int st) {
        const int kbase = kt * GBK;
        const uint32_t sA = sb + st * STAGE_BYTES;
        const uint32_t sB = sA + AS_BYTES;
#pragma unroll
        for (int i = 0; i < 4; i++) {
            int idx = tid + i * 256;
            int row = idx >> 3;
            int u   = idx & 7;
            int gr  = m0 + row;
            bool ok = (gr < M);
            const float* src = ok ? (A + (size_t)gr * KDIM + kbase + u * 4) : A;
            cp16(sA + row * (A_PITCH * 4) + u * 16, src, ok ? 16 : 0);
        }
#pragma unroll
        for (int i = 0; i < 4; i++) {
            int idx = tid + i * 256;
            int row = idx >> 5;
            int u   = idx & 31;
            int col = n0 + u * 4;
            bool ok = (col + 4 <= N);
            const float* src = ok ? (B + (size_t)(kbase + row) * N + col) : B;
            cp16(sB + row * (B_PITCH * 4) + u * 16, src, ok ? 16 : 0);
        }
    };

    auto compute = [&](int st) {
        const float* As = (const float*)(smem + st * STAGE_BYTES);
        const float* Bs = (const float*)(smem + st * STAGE_BYTES + AS_BYTES);
#pragma unroll
        for (int s = 0; s < 4; s++) {
            const int kk = s * 8;
            uint32_t af[2][4];
#pragma unroll
            for (int mi = 0; mi < 2; mi++) {
                int r0 = wm * 32 + mi * 16 + grp;
                af[mi][0] = __float_as_uint(As[r0 * A_PITCH + kk + tig]);
                af[mi][1] = __float_as_uint(As[(r0 + 8) * A_PITCH + kk + tig]);
                af[mi][2] = __float_as_uint(As[r0 * A_PITCH + kk + tig + 4]);
                af[mi][3] = __float_as_uint(As[(r0 + 8) * A_PITCH + kk + tig + 4]);
            }
#pragma unroll
            for (int h = 0; h < 2; h++) {
                uint32_t bf[4][2];
#pragma unroll
                for (int q = 0; q < 4; q++) {
                    int cn = wn * 64 + (h * 4 + q) * 8 + grp;
                    bf[q][0] = __float_as_uint(Bs[(kk + tig) * B_PITCH + cn]);
                    bf[q][1] = __float_as_uint(Bs[(kk + tig + 4) * B_PITCH + cn]);
                }
#pragma unroll
                for (int q = 0; q < 4; q++) {
                    mma8(acc[0][h * 4 + q], af[0], bf[q][0], bf[q][1]);
                    mma8(acc[1][h * 4 + q], af[1], bf[q][0], bf[q][1]);
                }
            }
        }
    };

    issue(0, 0); CP_COMMIT();
    issue(1, 1); CP_COMMIT();
    for (int kt = 0; kt < GKT; kt++) {
        CP_WAIT1();
        __syncthreads();
        const int nx = kt + 2;
        if (nx < GKT) issue(nx, nx % 3);
        CP_COMMIT();
        compute(kt % 3);
    }

#pragma unroll
    for (int ni = 0; ni < 8; ni++) {
        int col = n0 + wn * 64 + ni * 8 + tig * 2;
        if (col >= N) continue;
        float bv0 = __ldg(bias + col);
        float bv1 = __ldg(bias + col + 1);
#pragma unroll
        for (int mi = 0; mi < 2; mi++) {
            int rbase = m0 + wm * 32 + mi * 16 + grp;
#pragma unroll
            for (int h = 0; h < 2; h++) {
                int r = rbase + h * 8;
                if (r >= M) continue;
                float x0 = acc[mi][ni][h * 2 + 0] + bv0;
                float x1 = acc[mi][ni][h * 2 + 1] + bv1;
                if (RELU) { x0 = fmaxf(x0, 0.f); x1 = fmaxf(x1, 0.f); }
                if (ROUND) {
                    x0 = __uint_as_float(f2tf(x0));
                    x1 = __uint_as_float(f2tf(x1));
                }
                float2 o; o.x = x0; o.y = x1;
                *reinterpret_cast<float2*>(Cout + (size_t)r * N + col) = o;
            }
        }
    }
}

// ===========================================================================
// Launch
// ===========================================================================
extern "C" void kernel_launch(void* const* d_in, const int* in_sizes, int n_in,
                              void* d_out, int out_size)
{
    const float* feat = (const float*)d_in[0];
    const int*   src  = (const int*)d_in[1];
    const int*   dst  = (const int*)d_in[2];
    const float* W0   = (const float*)d_in[3];
    const float* b0   = (const float*)d_in[4];
    const float* W1   = (const float*)d_in[5];
    const float* b1   = (const float*)d_in[6];
    const float* W2   = (const float*)d_in[7];
    const float* b2   = (const float*)d_in[8];
    const float* Wc   = (const float*)d_in[9];
    const float* bc   = (const float*)d_in[10];

    const int n_nodes = in_sizes[0] / D;
    const int n_edges = in_sizes[1];
    const int n_cls   = in_sizes[10];

    float *h1, *h2, *agg, *wt;
    int *deg, *indptr, *cursor, *csr;
    cudaGetSymbolAddress((void**)&h1, g_h1);
    cudaGetSymbolAddress((void**)&h2, g_h2);
    cudaGetSymbolAddress((void**)&agg, g_agg);
    cudaGetSymbolAddress((void**)&wt, g_wt);
    cudaGetSymbolAddress((void**)&deg, g_deg);
    cudaGetSymbolAddress((void**)&indptr, g_indptr);
    cudaGetSymbolAddress((void**)&cursor, g_cursor);
    cudaGetSymbolAddress((void**)&csr, g_csr);

    float* W0t = wt;
    float* W1t = wt + 262144;
    float* W2t = wt + 524288;
    float* Wct = wt + 786432;

    cudaFuncSetAttribute(gin_gemm<true, false>,
                         cudaFuncAttributeMaxDynamicSharedMemorySize, GSMEM_TOTAL);
    cudaFuncSetAttribute(gin_gemm<true, true>,
                         cudaFuncAttributeMaxDynamicSharedMemorySize, GSMEM_TOTAL);
    cudaFuncSetAttribute(gin_gemm<false, false>,
                         cudaFuncAttributeMaxDynamicSharedMemorySize, GSMEM_TOTAL);

    const int eBlocks = (n_edges + 255) / 256;

    // ---- weight pre-conversion to tf32 ----
    cvt_tf32_kernel<<<(65536 + 255) / 256, 256>>>((const float4*)W0, (float4*)W0t, 65536);
    cvt_tf32_kernel<<<(65536 + 255) / 256, 256>>>((const float4*)W1, (float4*)W1t, 65536);
    cvt_tf32_kernel<<<(65536 + 255) / 256, 256>>>((const float4*)W2, (float4*)W2t, 65536);
    const int wc4 = (512 * n_cls) / 4;
    cvt_tf32_kernel<<<(wc4 + 255) / 256, 256>>>((const float4*)Wc, (float4*)Wct, wc4);

    // ---- CSR build ----
    cudaMemsetAsync(deg, 0, (size_t)n_nodes * sizeof(int));
    cudaMemsetAsync(cursor, 0, (size_t)n_nodes * sizeof(int));
    hist_kernel<<<eBlocks, 256>>>(dst, deg, n_edges);
    scan_kernel<<<1, 1024>>>(deg, indptr, n_nodes);
    fill_kernel<<<eBlocks, 256>>>(src, dst, indptr, cursor, csr, n_edges);

    dim3 gGrid((n_nodes + BM - 1) / BM, (D + BN - 1) / BN);
    dim3 cGrid((n_nodes + BM - 1) / BM, (n_cls + BN - 1) / BN);

    // Layer 0
    gather_agg<<<n_nodes, 128>>>((const float4*)feat, indptr, csr, (float4*)agg);
    gin_gemm<true, false><<<gGrid, 256, GSMEM_TOTAL>>>(agg, W0t, b0, h1, n_nodes, D);

    // Layer 1
    gather_agg<<<n_nodes, 128>>>((const float4*)h1, indptr, csr, (float4*)agg);
    gin_gemm<true, false><<<gGrid, 256, GSMEM_TOTAL>>>(agg, W1t, b1, h2, n_nodes, D);

    // Layer 2 (round output: it feeds the classifier's A directly)
    gather_agg<<<n_nodes, 128>>>((const float4*)h2, indptr, csr, (float4*)agg);
    gin_gemm<true, true><<<gGrid, 256, GSMEM_TOTAL>>>(agg, W2t, b2, h1, n_nodes, D);

    // Classifier (no relu, full-precision output)
    gin_gemm<false, false><<<cGrid, 256, GSMEM_TOTAL>>>(h1, Wct, bc, (float*)d_out,
                                                        n_nodes, n_cls);
}

// round 8
// speedup vs baseline: 3.4395x; 1.0229x over previous
#include <cuda_runtime.h>
#include <cstdint>

#define D 512
#define D4 128
#define BM 128
#define BN 128
#define KDIM 512

static const int MAX_NODES = 50000;
static const int MAX_EDGES = 400000;

__device__ float g_h1[(size_t)MAX_NODES * D];
__device__ float g_h2[(size_t)MAX_NODES * D];
__device__ float g_agg[(size_t)MAX_NODES * D];
__device__ float g_wt[3 * 512 * 512 + 512 * 64];   // tf32-rounded weights

__device__ int g_deg[MAX_NODES];
__device__ int g_indptr[MAX_NODES + 1];
__device__ int g_cursor[MAX_NODES];
__device__ int g_csr[MAX_EDGES];

// ===========================================================================
// helpers
// ===========================================================================
__device__ __forceinline__ uint32_t smem_to_u32(const void* p) {
    uint32_t a;
    asm("{ .reg .u64 t; cvta.to.shared.u64 t, %1; cvt.u32.u64 %0, t; }"
        : "=r"(a) : "l"(p));
    return a;
}

__device__ __forceinline__ uint32_t f2tf(float x)
{
    uint32_t r;
    asm("cvt.rna.tf32.f32 %0, %1;" : "=r"(r) : "f"(x));
    return r;
}

__device__ __forceinline__ void cp16(uint32_t dst, const void* src, int sz)
{
    asm volatile("cp.async.cg.shared.global [%0], [%1], 16, %2;"
                 :: "r"(dst), "l"(src), "r"(sz) : "memory");
}
#define CP_COMMIT() asm volatile("cp.async.commit_group;" ::: "memory")
#define CP_WAIT1()  asm volatile("cp.async.wait_group 1;" ::: "memory")

__device__ __forceinline__ void mma8(float* c, const uint32_t* a, uint32_t b0, uint32_t b1)
{
    asm volatile(
        "mma.sync.aligned.m16n8k8.row.col.f32.tf32.tf32.f32 "
        "{%0,%1,%2,%3}, {%4,%5,%6,%7}, {%8,%9}, {%0,%1,%2,%3};\n"
        : "+f"(c[0]), "+f"(c[1]), "+f"(c[2]), "+f"(c[3])
        : "r"(a[0]), "r"(a[1]), "r"(a[2]), "r"(a[3]), "r"(b0), "r"(b1));
}

// ===========================================================================
// weight pre-conversion to tf32 (rna)
// ===========================================================================
__global__ void cvt_tf32_kernel(const float4* __restrict__ in,
                                float4* __restrict__ out, int n4)
{
    int i = blockIdx.x * blockDim.x + threadIdx.x;
    if (i >= n4) return;
    float4 v = __ldg(in + i);
    float4 t;
    t.x = __uint_as_float(f2tf(v.x));
    t.y = __uint_as_float(f2tf(v.y));
    t.z = __uint_as_float(f2tf(v.z));
    t.w = __uint_as_float(f2tf(v.w));
    out[i] = t;
}

// ===========================================================================
// CSR build
// ===========================================================================
__global__ void hist_kernel(const int* __restrict__ dst, int* __restrict__ deg,
                            int n_edges)
{
    int e = blockIdx.x * blockDim.x + threadIdx.x;
    if (e < n_edges) atomicAdd(&deg[__ldg(dst + e)], 1);
}

__global__ void scan_kernel(const int* __restrict__ deg, int* __restrict__ indptr,
                            int n)
{
    const int T = 1024;
    __shared__ int sh[T];
    int t = threadIdx.x;
    int chunk = (n + T - 1) / T;
    int beg = t * chunk;
    int end = min(beg + chunk, n);
    int s = 0;
    for (int i = beg; i < end; i++) s += deg[i];
    sh[t] = s;
    __syncthreads();
    for (int off = 1; off < T; off <<= 1) {
        int v = sh[t];
        int u = (t >= off) ? sh[t - off] : 0;
        __syncthreads();
        sh[t] = v + u;
        __syncthreads();
    }
    int run = (t == 0) ? 0 : sh[t - 1];
    for (int i = beg; i < end; i++) { indptr[i] = run; run += deg[i]; }
    if (t == T - 1) indptr[n] = sh[T - 1];
}

__global__ void fill_kernel(const int* __restrict__ src, const int* __restrict__ dst,
                            const int* __restrict__ indptr, int* __restrict__ cursor,
                            int* __restrict__ csr, int n_edges)
{
    int e = blockIdx.x * blockDim.x + threadIdx.x;
    if (e >= n_edges) return;
    int d = __ldg(dst + e);
    int pos = __ldg(indptr + d) + atomicAdd(&cursor[d], 1);
    csr[pos] = __ldg(src + e);
}

// ===========================================================================
// Gather aggregation: out[i] = tf32_round( h[i] + sum_{j in N_in(i)} h[j] )
// ===========================================================================
__global__ __launch_bounds__(128)
void gather_agg(const float4* __restrict__ h, const int* __restrict__ indptr,
                const int* __restrict__ csr, float4* __restrict__ out)
{
    __shared__ int nb[128];
    const int node = blockIdx.x;
    const int t = threadIdx.x;
    float4 acc = __ldg(h + (size_t)node * D4 + t);
    const int beg = __ldg(indptr + node);
    const int end = __ldg(indptr + node + 1);
    for (int base = beg; base < end; base += 128) {
        int cnt = min(128, end - base);
        if (t < cnt) nb[t] = __ldg(csr + base + t);
        __syncthreads();
        int i = 0;
        for (; i + 4 <= cnt; i += 4) {
            float4 v0 = __ldg(h + (size_t)nb[i + 0] * D4 + t);
            float4 v1 = __ldg(h + (size_t)nb[i + 1] * D4 + t);
            float4 v2 = __ldg(h + (size_t)nb[i + 2] * D4 + t);
            float4 v3 = __ldg(h + (size_t)nb[i + 3] * D4 + t);
            acc.x += v0.x + v1.x + v2.x + v3.x;
            acc.y += v0.y + v1.y + v2.y + v3.y;
            acc.z += v0.z + v1.z + v2.z + v3.z;
            acc.w += v0.w + v1.w + v2.w + v3.w;
        }
        for (; i < cnt; i++) {
            float4 v = __ldg(h + (size_t)nb[i] * D4 + t);
            acc.x += v.x; acc.y += v.y; acc.z += v.z; acc.w += v.w;
        }
        __syncthreads();
    }
    float4 o;
    o.x = __uint_as_float(f2tf(acc.x));
    o.y = __uint_as_float(f2tf(acc.y));
    o.z = __uint_as_float(f2tf(acc.z));
    o.w = __uint_as_float(f2tf(acc.w));
    __stcs(out + (size_t)node * D4 + t, o);
}

// ===========================================================================
// tf32 mma.sync GEMM.  128 threads/CTA, 4 warps, 64x64 warp tiles,
// block 128x128, BK=32, cp.async 3-stage, pre-rounded tf32 operands.
// ===========================================================================
#define GBK 32
#define GKT (KDIM / GBK)          // 16
#define A_PITCH 36                // floats
#define B_PITCH 136               // floats
#define AS_BYTES (128 * A_PITCH * 4)          // 18432
#define BS_BYTES (GBK * B_PITCH * 4)          // 17408
#define STAGE_BYTES (AS_BYTES + BS_BYTES)     // 35840
#define GSMEM_TOTAL (3 * STAGE_BYTES)         // 107520

template<bool RELU, bool ROUND>
__global__ __launch_bounds__(128, 2)
void gin_gemm(const float* __restrict__ A, const float* __restrict__ B,
              const float* __restrict__ bias, float* __restrict__ Cout,
              int M, int N)
{
    extern __shared__ char smem[];
    const uint32_t sb = smem_to_u32(smem);

    const int tid  = threadIdx.x;
    const int wid  = tid >> 5;
    const int lane = tid & 31;
    const int wm   = wid & 1;        // 2 warps along M (64 rows each)
    const int wn   = wid >> 1;       // 2 warps along N (64 cols each)
    const int grp  = lane >> 2;
    const int tig  = lane & 3;

    const int m0 = blockIdx.x * BM;
    const int n0 = blockIdx.y * BN;

    float acc[4][8][4];
#pragma unroll
    for (int mi = 0; mi < 4; mi++)
#pragma unroll
        for (int ni = 0; ni < 8; ni++)
#pragma unroll
            for (int j = 0; j < 4; j++) acc[mi][ni][j] = 0.f;

    auto issue = [&](int kt, int st) {
        const int kbase = kt * GBK;
        const uint32_t sA = sb + st * STAGE_BYTES;
        const uint32_t sB = sA + AS_BYTES;
        // A: 128 rows x 32 floats = 1024 x 16B / 8 per thread
#pragma unroll
        for (int i = 0; i < 8; i++) {
            int idx = tid + i * 128;
            int row = idx >> 3;
            int u   = idx & 7;
            int gr  = m0 + row;
            bool ok = (gr < M);
            const float* src = ok ? (A + (size_t)gr * KDIM + kbase + u * 4) : A;
            cp16(sA + row * (A_PITCH * 4) + u * 16, src, ok ? 16 : 0);
        }
        // B: 32 k-rows x 128 floats = 1024 x 16B / 8 per thread
#pragma unroll
        for (int i = 0; i < 8; i++) {
            int idx = tid + i * 128;
            int row = idx >> 5;
            int u   = idx & 31;
            int col = n0 + u * 4;
            bool ok = (col + 4 <= N);
            const float* src = ok ? (B + (size_t)(kbase + row) * N + col) : B;
            cp16(sB + row * (B_PITCH * 4) + u * 16, src, ok ? 16 : 0);
        }
    };

    auto compute = [&](int st) {
        const float* As = (const float*)(smem + st * STAGE_BYTES);
        const float* Bs = (const float*)(smem + st * STAGE_BYTES + AS_BYTES);
#pragma unroll
        for (int s = 0; s < 4; s++) {
            const int kk = s * 8;
            uint32_t af[4][4];
#pragma unroll
            for (int mi = 0; mi < 4; mi++) {
                int r0 = wm * 64 + mi * 16 + grp;
                af[mi][0] = __float_as_uint(As[r0 * A_PITCH + kk + tig]);
                af[mi][1] = __float_as_uint(As[(r0 + 8) * A_PITCH + kk + tig]);
                af[mi][2] = __float_as_uint(As[r0 * A_PITCH + kk + tig + 4]);
                af[mi][3] = __float_as_uint(As[(r0 + 8) * A_PITCH + kk + tig + 4]);
            }
#pragma unroll
            for (int nt = 0; nt < 8; nt++) {
                int cn = wn * 64 + nt * 8 + grp;
                uint32_t b0 = __float_as_uint(Bs[(kk + tig) * B_PITCH + cn]);
                uint32_t b1 = __float_as_uint(Bs[(kk + tig + 4) * B_PITCH + cn]);
#pragma unroll
                for (int mi = 0; mi < 4; mi++)
                    mma8(acc[mi][nt], af[mi], b0, b1);
            }
        }
    };

    issue(0, 0); CP_COMMIT();
    issue(1, 1); CP_COMMIT();
    for (int kt = 0; kt < GKT; kt++) {
        CP_WAIT1();
        __syncthreads();
        const int nx = kt + 2;
        if (nx < GKT) issue(nx, nx % 3);
        CP_COMMIT();
        compute(kt % 3);
    }

    // ---- epilogue ----
#pragma unroll
    for (int nt = 0; nt < 8; nt++) {
        int col = n0 + wn * 64 + nt * 8 + tig * 2;
        if (col >= N) continue;
        float bv0 = __ldg(bias + col);
        float bv1 = __ldg(bias + col + 1);
#pragma unroll
        for (int mi = 0; mi < 4; mi++) {
            int rbase = m0 + wm * 64 + mi * 16 + grp;
#pragma unroll
            for (int h = 0; h < 2; h++) {
                int r = rbase + h * 8;
                if (r >= M) continue;
                float x0 = acc[mi][nt][h * 2 + 0] + bv0;
                float x1 = acc[mi][nt][h * 2 + 1] + bv1;
                if (RELU) { x0 = fmaxf(x0, 0.f); x1 = fmaxf(x1, 0.f); }
                if (ROUND) {
                    x0 = __uint_as_float(f2tf(x0));
                    x1 = __uint_as_float(f2tf(x1));
                }
                float2 o; o.x = x0; o.y = x1;
                *reinterpret_cast<float2*>(Cout + (size_t)r * N + col) = o;
            }
        }
    }
}

// ===========================================================================
// Launch
// ===========================================================================
extern "C" void kernel_launch(void* const* d_in, const int* in_sizes, int n_in,
                              void* d_out, int out_size)
{
    const float* feat = (const float*)d_in[0];
    const int*   src  = (const int*)d_in[1];
    const int*   dst  = (const int*)d_in[2];
    const float* W0   = (const float*)d_in[3];
    const float* b0   = (const float*)d_in[4];
    const float* W1   = (const float*)d_in[5];
    const float* b1   = (const float*)d_in[6];
    const float* W2   = (const float*)d_in[7];
    const float* b2   = (const float*)d_in[8];
    const float* Wc   = (const float*)d_in[9];
    const float* bc   = (const float*)d_in[10];

    const int n_nodes = in_sizes[0] / D;
    const int n_edges = in_sizes[1];
    const int n_cls   = in_sizes[10];

    float *h1, *h2, *agg, *wt;
    int *deg, *indptr, *cursor, *csr;
    cudaGetSymbolAddress((void**)&h1, g_h1);
    cudaGetSymbolAddress((void**)&h2, g_h2);
    cudaGetSymbolAddress((void**)&agg, g_agg);
    cudaGetSymbolAddress((void**)&wt, g_wt);
    cudaGetSymbolAddress((void**)&deg, g_deg);
    cudaGetSymbolAddress((void**)&indptr, g_indptr);
    cudaGetSymbolAddress((void**)&cursor, g_cursor);
    cudaGetSymbolAddress((void**)&csr, g_csr);

    float* W0t = wt;
    float* W1t = wt + 262144;
    float* W2t = wt + 524288;
    float* Wct = wt + 786432;

    cudaFuncSetAttribute(gin_gemm<true, false>,
                         cudaFuncAttributeMaxDynamicSharedMemorySize, GSMEM_TOTAL);
    cudaFuncSetAttribute(gin_gemm<true, true>,
                         cudaFuncAttributeMaxDynamicSharedMemorySize, GSMEM_TOTAL);
    cudaFuncSetAttribute(gin_gemm<false, false>,
                         cudaFuncAttributeMaxDynamicSharedMemorySize, GSMEM_TOTAL);

    const int eBlocks = (n_edges + 255) / 256;

    // ---- weight pre-conversion to tf32 ----
    cvt_tf32_kernel<<<(65536 + 255) / 256, 256>>>((const float4*)W0, (float4*)W0t, 65536);
    cvt_tf32_kernel<<<(65536 + 255) / 256, 256>>>((const float4*)W1, (float4*)W1t, 65536);
    cvt_tf32_kernel<<<(65536 + 255) / 256, 256>>>((const float4*)W2, (float4*)W2t, 65536);
    const int wc4 = (512 * n_cls) / 4;
    cvt_tf32_kernel<<<(wc4 + 255) / 256, 256>>>((const float4*)Wc, (float4*)Wct, wc4);

    // ---- CSR build ----
    cudaMemsetAsync(deg, 0, (size_t)n_nodes * sizeof(int));
    cudaMemsetAsync(cursor, 0, (size_t)n_nodes * sizeof(int));
    hist_kernel<<<eBlocks, 256>>>(dst, deg, n_edges);
    scan_kernel<<<1, 1024>>>(deg, indptr, n_nodes);
    fill_kernel<<<eBlocks, 256>>>(src, dst, indptr, cursor, csr, n_edges);

    dim3 gGrid((n_nodes + BM - 1) / BM, (D + BN - 1) / BN);
    dim3 cGrid((n_nodes + BM - 1) / BM, (n_cls + BN - 1) / BN);

    // Layer 0
    gather_agg<<<n_nodes, 128>>>((const float4*)feat, indptr, csr, (float4*)agg);
    gin_gemm<true, false><<<gGrid, 128, GSMEM_TOTAL>>>(agg, W0t, b0, h1, n_nodes, D);

    // Layer 1
    gather_agg<<<n_nodes, 128>>>((const float4*)h1, indptr, csr, (float4*)agg);
    gin_gemm<true, false><<<gGrid, 128, GSMEM_TOTAL>>>(agg, W1t, b1, h2, n_nodes, D);

    // Layer 2 (round output: feeds the classifier's A)
    gather_agg<<<n_nodes, 128>>>((const float4*)h2, indptr, csr, (float4*)agg);
    gin_gemm<true, true><<<gGrid, 128, GSMEM_TOTAL>>>(agg, W2t, b2, h1, n_nodes, D);

    // Classifier (no relu)
    gin_gemm<false, false><<<cGrid, 128, GSMEM_TOTAL>>>(h1, Wct, bc, (float*)d_out,
                                                        n_nodes, n_cls);
}

// round 9
// speedup vs baseline: 4.6011x; 1.3377x over previous
#include <cuda_runtime.h>
#include <cuda_fp16.h>
#include <cstdint>

#define D 512
#define D4 128
#define BM 128
#define BN 128
#define KDIM 512

static const int MAX_NODES = 50000;
static const int MAX_EDGES = 400000;

__device__ float  g_h1[(size_t)MAX_NODES * D];
__device__ float  g_h2[(size_t)MAX_NODES * D];
__device__ __half g_aggh[(size_t)MAX_NODES * D];
__device__ __half g_hh[(size_t)MAX_NODES * D];
__device__ __half g_wth[3 * 512 * 512 + 64 * 512];   // transposed fp16 weights

__device__ int g_deg[MAX_NODES];
__device__ int g_indptr[MAX_NODES + 1];
__device__ int g_cursor[MAX_NODES];
__device__ int g_csr[MAX_EDGES];

// ===========================================================================
// helpers
// ===========================================================================
__device__ __forceinline__ uint32_t smem_to_u32(const void* p) {
    uint32_t a;
    asm("{ .reg .u64 t; cvta.to.shared.u64 t, %1; cvt.u32.u64 %0, t; }"
        : "=r"(a) : "l"(p));
    return a;
}

__device__ __forceinline__ void cp16(uint32_t dst, const void* src, int sz)
{
    asm volatile("cp.async.cg.shared.global [%0], [%1], 16, %2;"
                 :: "r"(dst), "l"(src), "r"(sz) : "memory");
}
#define CP_COMMIT() asm volatile("cp.async.commit_group;" ::: "memory")
#define CP_WAIT1()  asm volatile("cp.async.wait_group 1;" ::: "memory")

__device__ __forceinline__ void mmaH(float* c, const uint32_t* a, uint32_t b0, uint32_t b1)
{
    asm volatile(
        "mma.sync.aligned.m16n8k16.row.col.f32.f16.f16.f32 "
        "{%0,%1,%2,%3}, {%4,%5,%6,%7}, {%8,%9}, {%0,%1,%2,%3};\n"
        : "+f"(c[0]), "+f"(c[1]), "+f"(c[2]), "+f"(c[3])
        : "r"(a[0]), "r"(a[1]), "r"(a[2]), "r"(a[3]), "r"(b0), "r"(b1));
}

// ===========================================================================
// weight transpose + fp16 conversion:  out[n][k] = (half)in[k][n]
// ===========================================================================
__global__ void transpose_half_kernel(const float* __restrict__ in,
                                      __half* __restrict__ out,
                                      int K, int Ncols)
{
    __shared__ float tile[32][33];
    const int k0 = blockIdx.x * 32;
    const int n0 = blockIdx.y * 32;
    const int tx = threadIdx.x;
    const int ty = threadIdx.y;
#pragma unroll
    for (int i = 0; i < 32; i += 8) {
        int k = k0 + ty + i, n = n0 + tx;
        tile[ty + i][tx] = (k < K && n < Ncols) ? __ldg(in + (size_t)k * Ncols + n) : 0.f;
    }
    __syncthreads();
#pragma unroll
    for (int i = 0; i < 32; i += 8) {
        int n = n0 + ty + i, k = k0 + tx;
        if (n < Ncols && k < K)
            out[(size_t)n * K + k] = __float2half_rn(tile[tx][ty + i]);
    }
}

// ===========================================================================
// CSR build
// ===========================================================================
__global__ void hist_kernel(const int* __restrict__ dst, int* __restrict__ deg,
                            int n_edges)
{
    int e = blockIdx.x * blockDim.x + threadIdx.x;
    if (e < n_edges) atomicAdd(&deg[__ldg(dst + e)], 1);
}

__global__ void scan_kernel(const int* __restrict__ deg, int* __restrict__ indptr,
                            int n)
{
    const int T = 1024;
    __shared__ int sh[T];
    int t = threadIdx.x;
    int chunk = (n + T - 1) / T;
    int beg = t * chunk;
    int end = min(beg + chunk, n);
    int s = 0;
    for (int i = beg; i < end; i++) s += deg[i];
    sh[t] = s;
    __syncthreads();
    for (int off = 1; off < T; off <<= 1) {
        int v = sh[t];
        int u = (t >= off) ? sh[t - off] : 0;
        __syncthreads();
        sh[t] = v + u;
        __syncthreads();
    }
    int run = (t == 0) ? 0 : sh[t - 1];
    for (int i = beg; i < end; i++) { indptr[i] = run; run += deg[i]; }
    if (t == T - 1) indptr[n] = sh[T - 1];
}

__global__ void fill_kernel(const int* __restrict__ src, const int* __restrict__ dst,
                            const int* __restrict__ indptr, int* __restrict__ cursor,
                            int* __restrict__ csr, int n_edges)
{
    int e = blockIdx.x * blockDim.x + threadIdx.x;
    if (e >= n_edges) return;
    int d = __ldg(dst + e);
    int pos = __ldg(indptr + d) + atomicAdd(&cursor[d], 1);
    csr[pos] = __ldg(src + e);
}

// ===========================================================================
// Gather aggregation: out_fp16[i] = rn( h[i] + sum_{j in N_in(i)} h[j] )
// fp32 accumulation, single fp16 rounding at the end.
// ===========================================================================
__global__ __launch_bounds__(128)
void gather_agg(const float4* __restrict__ h, const int* __restrict__ indptr,
                const int* __restrict__ csr, float2* __restrict__ out)
{
    __shared__ int nb[128];
    const int node = blockIdx.x;
    const int t = threadIdx.x;
    float4 acc = __ldg(h + (size_t)node * D4 + t);
    const int beg = __ldg(indptr + node);
    const int end = __ldg(indptr + node + 1);
    for (int base = beg; base < end; base += 128) {
        int cnt = min(128, end - base);
        if (t < cnt) nb[t] = __ldg(csr + base + t);
        __syncthreads();
        int i = 0;
        for (; i + 4 <= cnt; i += 4) {
            float4 v0 = __ldg(h + (size_t)nb[i + 0] * D4 + t);
            float4 v1 = __ldg(h + (size_t)nb[i + 1] * D4 + t);
            float4 v2 = __ldg(h + (size_t)nb[i + 2] * D4 + t);
            float4 v3 = __ldg(h + (size_t)nb[i + 3] * D4 + t);
            acc.x += v0.x + v1.x + v2.x + v3.x;
            acc.y += v0.y + v1.y + v2.y + v3.y;
            acc.z += v0.z + v1.z + v2.z + v3.z;
            acc.w += v0.w + v1.w + v2.w + v3.w;
        }
        for (; i < cnt; i++) {
            float4 v = __ldg(h + (size_t)nb[i] * D4 + t);
            acc.x += v.x; acc.y += v.y; acc.z += v.z; acc.w += v.w;
        }
        __syncthreads();
    }
    __half2 p0 = __floats2half2_rn(acc.x, acc.y);
    __half2 p1 = __floats2half2_rn(acc.z, acc.w);
    float2 o;
    o.x = __uint_as_float(*reinterpret_cast<uint32_t*>(&p0));
    o.y = __uint_as_float(*reinterpret_cast<uint32_t*>(&p1));
    __stcs(out + (size_t)node * D4 + t, o);
}

// ===========================================================================
// fp16 mma.sync GEMM.  128 threads, 4 warps (2x2), 64x64 warp tiles,
// block 128x128, BK=32, cp.async 3-stage.
// A half [M,512] row-major; Bt half [N,512] (pre-transposed weights, k-contig).
// C = act(A @ Bt^T + bias); OUTH selects fp16 vs fp32 output.
// ===========================================================================
#define HBK 32
#define HKT (KDIM / HBK)          // 16
#define HPITCH 40                 // halves per row (80B), conflict-free
#define HAS_B (128 * HPITCH * 2)  // 10240
#define HBS_B (128 * HPITCH * 2)  // 10240
#define HSTG  (HAS_B + HBS_B)     // 20480
#define HSMEM (3 * HSTG)          // 61440

template<bool RELU, bool OUTH>
__global__ __launch_bounds__(128, 2)
void gin_hgemm(const __half* __restrict__ A, const __half* __restrict__ Bt,
               const float* __restrict__ bias, void* __restrict__ CoutV,
               int M, int N)
{
    extern __shared__ char smem[];
    const uint32_t sb = smem_to_u32(smem);

    const int tid  = threadIdx.x;
    const int wid  = tid >> 5;
    const int lane = tid & 31;
    const int wm   = wid & 1;
    const int wn   = wid >> 1;
    const int grp  = lane >> 2;
    const int tig  = lane & 3;

    const int m0 = blockIdx.x * BM;
    const int n0 = blockIdx.y * BN;

    float acc[4][8][4];
#pragma unroll
    for (int mi = 0; mi < 4; mi++)
#pragma unroll
        for (int ni = 0; ni < 8; ni++)
#pragma unroll
            for (int j = 0; j < 4; j++) acc[mi][ni][j] = 0.f;

    auto issue = [&](int kt, int st) {
        const int kbase = kt * HBK;               // in halves
        const uint32_t sA = sb + st * HSTG;
        const uint32_t sB = sA + HAS_B;
        // A: 128 rows x 32 halves (64B) = 512 x 16B chunks / 4 per thread
#pragma unroll
        for (int i = 0; i < 4; i++) {
            int idx = tid + i * 128;
            int row = idx >> 2;
            int u   = idx & 3;
            int gr  = m0 + row;
            bool ok = (gr < M);
            const __half* src = ok ? (A + (size_t)gr * KDIM + kbase + u * 8) : A;
            cp16(sA + row * (HPITCH * 2) + u * 16, src, ok ? 16 : 0);
        }
        // B: 128 n-rows x 32 halves = 512 x 16B chunks / 4 per thread
#pragma unroll
        for (int i = 0; i < 4; i++) {
            int idx = tid + i * 128;
            int row = idx >> 2;
            int u   = idx & 3;
            int gn  = n0 + row;
            bool ok = (gn < N);
            const __half* src = ok ? (Bt + (size_t)gn * KDIM + kbase + u * 8) : Bt;
            cp16(sB + row * (HPITCH * 2) + u * 16, src, ok ? 16 : 0);
        }
    };

    auto compute = [&](int st) {
        const uint32_t* As = (const uint32_t*)(smem + st * HSTG);
        const uint32_t* Bs = (const uint32_t*)(smem + st * HSTG + HAS_B);
#pragma unroll
        for (int s = 0; s < 2; s++) {
            const int base = 8 * s;               // 4B-unit offset of k16 slice
            uint32_t af[4][4];
#pragma unroll
            for (int mi = 0; mi < 4; mi++) {
                int r0 = wm * 64 + mi * 16 + grp;
                af[mi][0] = As[r0 * 20 + base + tig];
                af[mi][1] = As[(r0 + 8) * 20 + base + tig];
                af[mi][2] = As[r0 * 20 + base + 4 + tig];
                af[mi][3] = As[(r0 + 8) * 20 + base + 4 + tig];
            }
#pragma unroll
            for (int nt = 0; nt < 8; nt++) {
                int cn = wn * 64 + nt * 8 + grp;
                uint32_t b0 = Bs[cn * 20 + base + tig];
                uint32_t b1 = Bs[cn * 20 + base + 4 + tig];
#pragma unroll
                for (int mi = 0; mi < 4; mi++)
                    mmaH(acc[mi][nt], af[mi], b0, b1);
            }
        }
    };

    issue(0, 0); CP_COMMIT();
    issue(1, 1); CP_COMMIT();
    for (int kt = 0; kt < HKT; kt++) {
        CP_WAIT1();
        __syncthreads();
        const int nx = kt + 2;
        if (nx < HKT) issue(nx, nx % 3);
        CP_COMMIT();
        compute(kt % 3);
    }

    // ---- epilogue ----
#pragma unroll
    for (int nt = 0; nt < 8; nt++) {
        int col = n0 + wn * 64 + nt * 8 + tig * 2;
        if (col >= N) continue;
        float bv0 = __ldg(bias + col);
        float bv1 = __ldg(bias + col + 1);
#pragma unroll
        for (int mi = 0; mi < 4; mi++) {
            int rbase = m0 + wm * 64 + mi * 16 + grp;
#pragma unroll
            for (int h = 0; h < 2; h++) {
                int r = rbase + h * 8;
                if (r >= M) continue;
                float x0 = acc[mi][nt][h * 2 + 0] + bv0;
                float x1 = acc[mi][nt][h * 2 + 1] + bv1;
                if (RELU) { x0 = fmaxf(x0, 0.f); x1 = fmaxf(x1, 0.f); }
                if (OUTH) {
                    __half2 p = __floats2half2_rn(x0, x1);
                    *reinterpret_cast<__half2*>((__half*)CoutV + (size_t)r * N + col) = p;
                } else {
                    float2 o; o.x = x0; o.y = x1;
                    *reinterpret_cast<float2*>((float*)CoutV + (size_t)r * N + col) = o;
                }
            }
        }
    }
}

// ===========================================================================
// Launch
// ===========================================================================
extern "C" void kernel_launch(void* const* d_in, const int* in_sizes, int n_in,
                              void* d_out, int out_size)
{
    const float* feat = (const float*)d_in[0];
    const int*   src  = (const int*)d_in[1];
    const int*   dst  = (const int*)d_in[2];
    const float* W0   = (const float*)d_in[3];
    const float* b0   = (const float*)d_in[4];
    const float* W1   = (const float*)d_in[5];
    const float* b1   = (const float*)d_in[6];
    const float* W2   = (const float*)d_in[7];
    const float* b2   = (const float*)d_in[8];
    const float* Wc   = (const float*)d_in[9];
    const float* bc   = (const float*)d_in[10];

    const int n_nodes = in_sizes[0] / D;
    const int n_edges = in_sizes[1];
    const int n_cls   = in_sizes[10];

    float *h1, *h2;
    __half *aggh, *hh, *wth;
    int *deg, *indptr, *cursor, *csr;
    cudaGetSymbolAddress((void**)&h1, g_h1);
    cudaGetSymbolAddress((void**)&h2, g_h2);
    cudaGetSymbolAddress((void**)&aggh, g_aggh);
    cudaGetSymbolAddress((void**)&hh, g_hh);
    cudaGetSymbolAddress((void**)&wth, g_wth);
    cudaGetSymbolAddress((void**)&deg, g_deg);
    cudaGetSymbolAddress((void**)&indptr, g_indptr);
    cudaGetSymbolAddress((void**)&cursor, g_cursor);
    cudaGetSymbolAddress((void**)&csr, g_csr);

    __half* W0t = wth;
    __half* W1t = wth + 262144;
    __half* W2t = wth + 524288;
    __half* Wct = wth + 786432;

    cudaFuncSetAttribute(gin_hgemm<true, false>,
                         cudaFuncAttributeMaxDynamicSharedMemorySize, HSMEM);
    cudaFuncSetAttribute(gin_hgemm<true, true>,
                         cudaFuncAttributeMaxDynamicSharedMemorySize, HSMEM);
    cudaFuncSetAttribute(gin_hgemm<false, false>,
                         cudaFuncAttributeMaxDynamicSharedMemorySize, HSMEM);

    const int eBlocks = (n_edges + 255) / 256;

    // ---- weight transpose + fp16 conversion (once per call) ----
    {
        dim3 tb(32, 8);
        dim3 tg(16, 16);
        transpose_half_kernel<<<tg, tb>>>(W0, W0t, KDIM, 512);
        transpose_half_kernel<<<tg, tb>>>(W1, W1t, KDIM, 512);
        transpose_half_kernel<<<tg, tb>>>(W2, W2t, KDIM, 512);
        dim3 tgc(16, (n_cls + 31) / 32);
        transpose_half_kernel<<<tgc, tb>>>(Wc, Wct, KDIM, n_cls);
    }

    // ---- CSR build ----
    cudaMemsetAsync(deg, 0, (size_t)n_nodes * sizeof(int));
    cudaMemsetAsync(cursor, 0, (size_t)n_nodes * sizeof(int));
    hist_kernel<<<eBlocks, 256>>>(dst, deg, n_edges);
    scan_kernel<<<1, 1024>>>(deg, indptr, n_nodes);
    fill_kernel<<<eBlocks, 256>>>(src, dst, indptr, cursor, csr, n_edges);

    dim3 gGrid((n_nodes + BM - 1) / BM, (D + BN - 1) / BN);
    dim3 cGrid((n_nodes + BM - 1) / BM, (n_cls + BN - 1) / BN);

    // Layer 0
    gather_agg<<<n_nodes, 128>>>((const float4*)feat, indptr, csr, (float2*)aggh);
    gin_hgemm<true, false><<<gGrid, 128, HSMEM>>>(aggh, W0t, b0, h1, n_nodes, D);

    // Layer 1
    gather_agg<<<n_nodes, 128>>>((const float4*)h1, indptr, csr, (float2*)aggh);
    gin_hgemm<true, false><<<gGrid, 128, HSMEM>>>(aggh, W1t, b1, h2, n_nodes, D);

    // Layer 2 -> fp16 output feeds classifier directly
    gather_agg<<<n_nodes, 128>>>((const float4*)h2, indptr, csr, (float2*)aggh);
    gin_hgemm<true, true><<<gGrid, 128, HSMEM>>>(aggh, W2t, b2, hh, n_nodes, D);

    // Classifier (fp16 A, fp32 out)
    gin_hgemm<false, false><<<cGrid, 128, HSMEM>>>(hh, Wct, bc, (float*)d_out,
                                                   n_nodes, n_cls);
}

// round 10
// speedup vs baseline: 5.3636x; 1.1657x over previous
#include <cuda_runtime.h>
#include <cuda_fp16.h>
#include <cstdint>

#define D 512
#define KDIM 512
#define BM 128
#define BN 128

static const int MAX_NODES = 50000;
static const int MAX_EDGES = 400000;

__device__ __half g_feath[(size_t)MAX_NODES * D];
__device__ __half g_hh1[(size_t)MAX_NODES * D];
__device__ __half g_hh2[(size_t)MAX_NODES * D];
__device__ __half g_aggh[(size_t)MAX_NODES * D];
__device__ __half g_wth[3 * 512 * 512 + 64 * 512];   // transposed fp16 weights

__device__ int g_deg[MAX_NODES];
__device__ int g_indptr[MAX_NODES + 1];
__device__ int g_cursor[MAX_NODES];
__device__ int g_csr[MAX_EDGES];

// ===========================================================================
// helpers
// ===========================================================================
__device__ __forceinline__ uint32_t smem_to_u32(const void* p) {
    uint32_t a;
    asm("{ .reg .u64 t; cvta.to.shared.u64 t, %1; cvt.u32.u64 %0, t; }"
        : "=r"(a) : "l"(p));
    return a;
}

__device__ __forceinline__ void cp16(uint32_t dst, const void* src, int sz)
{
    asm volatile("cp.async.cg.shared.global [%0], [%1], 16, %2;"
                 :: "r"(dst), "l"(src), "r"(sz) : "memory");
}
#define CP_COMMIT() asm volatile("cp.async.commit_group;" ::: "memory")
#define CP_WAIT1()  asm volatile("cp.async.wait_group 1;" ::: "memory")

__device__ __forceinline__ void mmaH(float* c, const uint32_t* a, uint32_t b0, uint32_t b1)
{
    asm volatile(
        "mma.sync.aligned.m16n8k16.row.col.f32.f16.f16.f32 "
        "{%0,%1,%2,%3}, {%4,%5,%6,%7}, {%8,%9}, {%0,%1,%2,%3};\n"
        : "+f"(c[0]), "+f"(c[1]), "+f"(c[2]), "+f"(c[3])
        : "r"(a[0]), "r"(a[1]), "r"(a[2]), "r"(a[3]), "r"(b0), "r"(b1));
}

// ===========================================================================
// feat -> fp16  (each thread: 8 floats -> 8 halves)
// ===========================================================================
__global__ void feat2half_kernel(const float4* __restrict__ in,
                                 uint4* __restrict__ out, int n8)
{
    int i = blockIdx.x * blockDim.x + threadIdx.x;
    if (i >= n8) return;
    float4 a = __ldg(in + i * 2);
    float4 b = __ldg(in + i * 2 + 1);
    __half2 p0 = __floats2half2_rn(a.x, a.y);
    __half2 p1 = __floats2half2_rn(a.z, a.w);
    __half2 p2 = __floats2half2_rn(b.x, b.y);
    __half2 p3 = __floats2half2_rn(b.z, b.w);
    uint4 o;
    o.x = *reinterpret_cast<uint32_t*>(&p0);
    o.y = *reinterpret_cast<uint32_t*>(&p1);
    o.z = *reinterpret_cast<uint32_t*>(&p2);
    o.w = *reinterpret_cast<uint32_t*>(&p3);
    out[i] = o;
}

// ===========================================================================
// weight transpose + fp16:  out[n][k] = (half)in[k][n]
// ===========================================================================
__global__ void transpose_half_kernel(const float* __restrict__ in,
                                      __half* __restrict__ out,
                                      int K, int Ncols)
{
    __shared__ float tile[32][33];
    const int k0 = blockIdx.x * 32;
    const int n0 = blockIdx.y * 32;
    const int tx = threadIdx.x;
    const int ty = threadIdx.y;
#pragma unroll
    for (int i = 0; i < 32; i += 8) {
        int k = k0 + ty + i, n = n0 + tx;
        tile[ty + i][tx] = (k < K && n < Ncols) ? __ldg(in + (size_t)k * Ncols + n) : 0.f;
    }
    __syncthreads();
#pragma unroll
    for (int i = 0; i < 32; i += 8) {
        int n = n0 + ty + i, k = k0 + tx;
        if (n < Ncols && k < K)
            out[(size_t)n * K + k] = __float2half_rn(tile[tx][ty + i]);
    }
}

// ===========================================================================
// CSR build
// ===========================================================================
__global__ void hist_kernel(const int* __restrict__ dst, int* __restrict__ deg,
                            int n_edges)
{
    int e = blockIdx.x * blockDim.x + threadIdx.x;
    if (e < n_edges) atomicAdd(&deg[__ldg(dst + e)], 1);
}

__global__ void scan_kernel(const int* __restrict__ deg, int* __restrict__ indptr,
                            int n)
{
    const int T = 1024;
    __shared__ int sh[T];
    int t = threadIdx.x;
    int chunk = (n + T - 1) / T;
    int beg = t * chunk;
    int end = min(beg + chunk, n);
    int s = 0;
    for (int i = beg; i < end; i++) s += deg[i];
    sh[t] = s;
    __syncthreads();
    for (int off = 1; off < T; off <<= 1) {
        int v = sh[t];
        int u = (t >= off) ? sh[t - off] : 0;
        __syncthreads();
        sh[t] = v + u;
        __syncthreads();
    }
    int run = (t == 0) ? 0 : sh[t - 1];
    for (int i = beg; i < end; i++) { indptr[i] = run; run += deg[i]; }
    if (t == T - 1) indptr[n] = sh[T - 1];
}

__global__ void fill_kernel(const int* __restrict__ src, const int* __restrict__ dst,
                            const int* __restrict__ indptr, int* __restrict__ cursor,
                            int* __restrict__ csr, int n_edges)
{
    int e = blockIdx.x * blockDim.x + threadIdx.x;
    if (e >= n_edges) return;
    int d = __ldg(dst + e);
    int pos = __ldg(indptr + d) + atomicAdd(&cursor[d], 1);
    csr[pos] = __ldg(src + e);
}

// ===========================================================================
// Gather aggregation (fp16 in, fp32 accum, fp16 out):
//   out[i] = rn( h[i] + sum_{j in N_in(i)} h[j] )
// Row = 1024B = 128 x uint2; thread t owns 4 halves.
// ===========================================================================
__global__ __launch_bounds__(128)
void gather_agg_h(const uint2* __restrict__ h, const int* __restrict__ indptr,
                  const int* __restrict__ csr, uint2* __restrict__ out)
{
    __shared__ int nb[128];
    const int node = blockIdx.x;
    const int t = threadIdx.x;

    uint2 sv = __ldg(h + (size_t)node * 128 + t);
    float2 f0 = __half22float2(*reinterpret_cast<__half2*>(&sv.x));
    float2 f1 = __half22float2(*reinterpret_cast<__half2*>(&sv.y));
    float a0 = f0.x, a1 = f0.y, a2 = f1.x, a3 = f1.y;

    const int beg = __ldg(indptr + node);
    const int end = __ldg(indptr + node + 1);
    for (int base = beg; base < end; base += 128) {
        int cnt = min(128, end - base);
        if (t < cnt) nb[t] = __ldg(csr + base + t);
        __syncthreads();
        for (int i = 0; i < cnt; i++) {
            uint2 v = __ldg(h + (size_t)nb[i] * 128 + t);
            float2 g0 = __half22float2(*reinterpret_cast<__half2*>(&v.x));
            float2 g1 = __half22float2(*reinterpret_cast<__half2*>(&v.y));
            a0 += g0.x; a1 += g0.y; a2 += g1.x; a3 += g1.y;
        }
        __syncthreads();
    }
    __half2 p0 = __floats2half2_rn(a0, a1);
    __half2 p1 = __floats2half2_rn(a2, a3);
    uint2 o;
    o.x = *reinterpret_cast<uint32_t*>(&p0);
    o.y = *reinterpret_cast<uint32_t*>(&p1);
    __stcs(out + (size_t)node * 128 + t, o);
}

// ===========================================================================
// fp16 mma.sync GEMM.  128 threads, 4 warps (2x2), 64x64 warp tiles,
// block 128x128, BK=64, cp.async 3-stage.
// A half [M,512]; Bt half [N,512] (k-contig).  C = act(A @ Bt^T + bias).
// ===========================================================================
#define HBK 64
#define HKT (KDIM / HBK)          // 8
#define HPITCH 72                 // halves per row (144B)
#define HPITCH32 36               // uint32 per row
#define HAS_B (128 * HPITCH * 2)  // 18432
#define HSTG  (2 * HAS_B)         // 36864
#define HSMEM (3 * HSTG)          // 110592

template<bool RELU, bool OUTH>
__global__ __launch_bounds__(128, 2)
void gin_hgemm(const __half* __restrict__ A, const __half* __restrict__ Bt,
               const float* __restrict__ bias, void* __restrict__ CoutV,
               int M, int N)
{
    extern __shared__ char smem[];
    const uint32_t sb = smem_to_u32(smem);

    const int tid  = threadIdx.x;
    const int wid  = tid >> 5;
    const int lane = tid & 31;
    const int wm   = wid & 1;
    const int wn   = wid >> 1;
    const int grp  = lane >> 2;
    const int tig  = lane & 3;

    const int m0 = blockIdx.x * BM;
    const int n0 = blockIdx.y * BN;

    float acc[4][8][4];
#pragma unroll
    for (int mi = 0; mi < 4; mi++)
#pragma unroll
        for (int ni = 0; ni < 8; ni++)
#pragma unroll
            for (int j = 0; j < 4; j++) acc[mi][ni][j] = 0.f;

    auto issue = [&](int kt, int st) {
        const int kbase = kt * HBK;               // halves
        const uint32_t sA = sb + st * HSTG;
        const uint32_t sB = sA + HAS_B;
        // A: 128 rows x 64 halves (128B = 8 chunks) = 1024 chunks / 8 per thread
#pragma unroll
        for (int i = 0; i < 8; i++) {
            int idx = tid + i * 128;
            int row = idx >> 3;
            int u   = idx & 7;
            int gr  = m0 + row;
            bool ok = (gr < M);
            const __half* src = ok ? (A + (size_t)gr * KDIM + kbase + u * 8) : A;
            cp16(sA + row * (HPITCH * 2) + u * 16, src, ok ? 16 : 0);
        }
#pragma unroll
        for (int i = 0; i < 8; i++) {
            int idx = tid + i * 128;
            int row = idx >> 3;
            int u   = idx & 7;
            int gn  = n0 + row;
            bool ok = (gn < N);
            const __half* src = ok ? (Bt + (size_t)gn * KDIM + kbase + u * 8) : Bt;
            cp16(sB + row * (HPITCH * 2) + u * 16, src, ok ? 16 : 0);
        }
    };

    auto compute = [&](int st) {
        const uint32_t* As = (const uint32_t*)(smem + st * HSTG);
        const uint32_t* Bs = (const uint32_t*)(smem + st * HSTG + HAS_B);
#pragma unroll
        for (int s = 0; s < 4; s++) {
            const int base = 8 * s;               // u32 offset of k16 slice
            uint32_t af[4][4];
#pragma unroll
            for (int mi = 0; mi < 4; mi++) {
                int r0 = wm * 64 + mi * 16 + grp;
                af[mi][0] = As[r0 * HPITCH32 + base + tig];
                af[mi][1] = As[(r0 + 8) * HPITCH32 + base + tig];
                af[mi][2] = As[r0 * HPITCH32 + base + 4 + tig];
                af[mi][3] = As[(r0 + 8) * HPITCH32 + base + 4 + tig];
            }
#pragma unroll
            for (int nt = 0; nt < 8; nt++) {
                int cn = wn * 64 + nt * 8 + grp;
                uint32_t b0 = Bs[cn * HPITCH32 + base + tig];
                uint32_t b1 = Bs[cn * HPITCH32 + base + 4 + tig];
#pragma unroll
                for (int mi = 0; mi < 4; mi++)
                    mmaH(acc[mi][nt], af[mi], b0, b1);
            }
        }
    };

    issue(0, 0); CP_COMMIT();
    issue(1, 1); CP_COMMIT();
    for (int kt = 0; kt < HKT; kt++) {
        CP_WAIT1();
        __syncthreads();
        const int nx = kt + 2;
        if (nx < HKT) issue(nx, nx % 3);
        CP_COMMIT();
        compute(kt % 3);
    }

    // ---- epilogue ----
#pragma unroll
    for (int nt = 0; nt < 8; nt++) {
        int col = n0 + wn * 64 + nt * 8 + tig * 2;
        if (col >= N) continue;
        float bv0 = __ldg(bias + col);
        float bv1 = __ldg(bias + col + 1);
#pragma unroll
        for (int mi = 0; mi < 4; mi++) {
            int rbase = m0 + wm * 64 + mi * 16 + grp;
#pragma unroll
            for (int h = 0; h < 2; h++) {
                int r = rbase + h * 8;
                if (r >= M) continue;
                float x0 = acc[mi][nt][h * 2 + 0] + bv0;
                float x1 = acc[mi][nt][h * 2 + 1] + bv1;
                if (RELU) { x0 = fmaxf(x0, 0.f); x1 = fmaxf(x1, 0.f); }
                if (OUTH) {
                    __half2 p = __floats2half2_rn(x0, x1);
                    *reinterpret_cast<__half2*>((__half*)CoutV + (size_t)r * N + col) = p;
                } else {
                    float2 o; o.x = x0; o.y = x1;
                    *reinterpret_cast<float2*>((float*)CoutV + (size_t)r * N + col) = o;
                }
            }
        }
    }
}

// ===========================================================================
// Launch
// ===========================================================================
extern "C" void kernel_launch(void* const* d_in, const int* in_sizes, int n_in,
                              void* d_out, int out_size)
{
    const float* feat = (const float*)d_in[0];
    const int*   src  = (const int*)d_in[1];
    const int*   dst  = (const int*)d_in[2];
    const float* W0   = (const float*)d_in[3];
    const float* b0   = (const float*)d_in[4];
    const float* W1   = (const float*)d_in[5];
    const float* b1   = (const float*)d_in[6];
    const float* W2   = (const float*)d_in[7];
    const float* b2   = (const float*)d_in[8];
    const float* Wc   = (const float*)d_in[9];
    const float* bc   = (const float*)d_in[10];

    const int n_nodes = in_sizes[0] / D;
    const int n_edges = in_sizes[1];
    const int n_cls   = in_sizes[10];

    __half *feath, *hh1, *hh2, *aggh, *wth;
    int *deg, *indptr, *cursor, *csr;
    cudaGetSymbolAddress((void**)&feath, g_feath);
    cudaGetSymbolAddress((void**)&hh1, g_hh1);
    cudaGetSymbolAddress((void**)&hh2, g_hh2);
    cudaGetSymbolAddress((void**)&aggh, g_aggh);
    cudaGetSymbolAddress((void**)&wth, g_wth);
    cudaGetSymbolAddress((void**)&deg, g_deg);
    cudaGetSymbolAddress((void**)&indptr, g_indptr);
    cudaGetSymbolAddress((void**)&cursor, g_cursor);
    cudaGetSymbolAddress((void**)&csr, g_csr);

    __half* W0t = wth;
    __half* W1t = wth + 262144;
    __half* W2t = wth + 524288;
    __half* Wct = wth + 786432;

    cudaFuncSetAttribute(gin_hgemm<true, true>,
                         cudaFuncAttributeMaxDynamicSharedMemorySize, HSMEM);
    cudaFuncSetAttribute(gin_hgemm<false, false>,
                         cudaFuncAttributeMaxDynamicSharedMemorySize, HSMEM);

    const int eBlocks = (n_edges + 255) / 256;

    // ---- setup: feat->fp16, weight transposes, CSR ----
    const int n8 = (n_nodes * D) / 8;
    feat2half_kernel<<<(n8 + 255) / 256, 256>>>((const float4*)feat,
                                                (uint4*)feath, n8);
    {
        dim3 tb(32, 8);
        dim3 tg(16, 16);
        transpose_half_kernel<<<tg, tb>>>(W0, W0t, KDIM, 512);
        transpose_half_kernel<<<tg, tb>>>(W1, W1t, KDIM, 512);
        transpose_half_kernel<<<tg, tb>>>(W2, W2t, KDIM, 512);
        dim3 tgc(16, (n_cls + 31) / 32);
        transpose_half_kernel<<<tgc, tb>>>(Wc, Wct, KDIM, n_cls);
    }
    cudaMemsetAsync(deg, 0, (size_t)n_nodes * sizeof(int));
    cudaMemsetAsync(cursor, 0, (size_t)n_nodes * sizeof(int));
    hist_kernel<<<eBlocks, 256>>>(dst, deg, n_edges);
    scan_kernel<<<1, 1024>>>(deg, indptr, n_nodes);
    fill_kernel<<<eBlocks, 256>>>(src, dst, indptr, cursor, csr, n_edges);

    dim3 gGrid((n_nodes + BM - 1) / BM, (D + BN - 1) / BN);
    dim3 cGrid((n_nodes + BM - 1) / BM, (n_cls + BN - 1) / BN);

    // Layer 0
    gather_agg_h<<<n_nodes, 128>>>((const uint2*)feath, indptr, csr, (uint2*)aggh);
    gin_hgemm<true, true><<<gGrid, 128, HSMEM>>>(aggh, W0t, b0, hh1, n_nodes, D);

    // Layer 1
    gather_agg_h<<<n_nodes, 128>>>((const uint2*)hh1, indptr, csr, (uint2*)aggh);
    gin_hgemm<true, true><<<gGrid, 128, HSMEM>>>(aggh, W1t, b1, hh2, n_nodes, D);

    // Layer 2
    gather_agg_h<<<n_nodes, 128>>>((const uint2*)hh2, indptr, csr, (uint2*)aggh);
    gin_hgemm<true, true><<<gGrid, 128, HSMEM>>>(aggh, W2t, b2, hh1, n_nodes, D);

    // Classifier (fp16 A, fp32 out)
    gin_hgemm<false, false><<<cGrid, 128, HSMEM>>>(hh1, Wct, bc, (float*)d_out,
                                                   n_nodes, n_cls);
}

// round 11
// speedup vs baseline: 5.7416x; 1.0705x over previous
#include <cuda_runtime.h>
#include <cuda_fp16.h>
#include <cstdint>

#define D 512
#define KDIM 512
#define BM 128
#define BN 128

static const int MAX_NODES = 50000;
static const int MAX_EDGES = 400000;

__device__ __half g_feath[(size_t)MAX_NODES * D];
__device__ __half g_hh1[(size_t)MAX_NODES * D];
__device__ __half g_hh2[(size_t)MAX_NODES * D];
__device__ __half g_aggh[(size_t)MAX_NODES * D];
__device__ __half g_wth[3 * 512 * 512 + 64 * 512];   // transposed fp16 weights

__device__ int g_deg[MAX_NODES];
__device__ int g_indptr[MAX_NODES + 1];
__device__ int g_cursor[MAX_NODES];
__device__ int g_csr[MAX_EDGES];

// ===========================================================================
// helpers
// ===========================================================================
__device__ __forceinline__ uint32_t smem_to_u32(const void* p) {
    uint32_t a;
    asm("{ .reg .u64 t; cvta.to.shared.u64 t, %1; cvt.u32.u64 %0, t; }"
        : "=r"(a) : "l"(p));
    return a;
}

__device__ __forceinline__ void cp16(uint32_t dst, const void* src, int sz)
{
    asm volatile("cp.async.cg.shared.global [%0], [%1], 16, %2;"
                 :: "r"(dst), "l"(src), "r"(sz) : "memory");
}
#define CP_COMMIT() asm volatile("cp.async.commit_group;" ::: "memory")
#define CP_WAIT1()  asm volatile("cp.async.wait_group 1;" ::: "memory")

__device__ __forceinline__ void mmaH(float* c, const uint32_t* a, uint32_t b0, uint32_t b1)
{
    asm volatile(
        "mma.sync.aligned.m16n8k16.row.col.f32.f16.f16.f32 "
        "{%0,%1,%2,%3}, {%4,%5,%6,%7}, {%8,%9}, {%0,%1,%2,%3};\n"
        : "+f"(c[0]), "+f"(c[1]), "+f"(c[2]), "+f"(c[3])
        : "r"(a[0]), "r"(a[1]), "r"(a[2]), "r"(a[3]), "r"(b0), "r"(b1));
}

__device__ __forceinline__ void ldsm4(uint32_t* r, uint32_t addr)
{
    asm volatile(
        "ldmatrix.sync.aligned.m8n8.x4.shared.b16 {%0,%1,%2,%3}, [%4];"
        : "=r"(r[0]), "=r"(r[1]), "=r"(r[2]), "=r"(r[3]) : "r"(addr));
}

// ===========================================================================
// feat -> fp16
// ===========================================================================
__global__ void feat2half_kernel(const float4* __restrict__ in,
                                 uint4* __restrict__ out, int n8)
{
    int i = blockIdx.x * blockDim.x + threadIdx.x;
    if (i >= n8) return;
    float4 a = __ldg(in + i * 2);
    float4 b = __ldg(in + i * 2 + 1);
    __half2 p0 = __floats2half2_rn(a.x, a.y);
    __half2 p1 = __floats2half2_rn(a.z, a.w);
    __half2 p2 = __floats2half2_rn(b.x, b.y);
    __half2 p3 = __floats2half2_rn(b.z, b.w);
    uint4 o;
    o.x = *reinterpret_cast<uint32_t*>(&p0);
    o.y = *reinterpret_cast<uint32_t*>(&p1);
    o.z = *reinterpret_cast<uint32_t*>(&p2);
    o.w = *reinterpret_cast<uint32_t*>(&p3);
    out[i] = o;
}

// ===========================================================================
// weight transpose + fp16:  out[n][k] = (half)in[k][n]
// ===========================================================================
__global__ void transpose_half_kernel(const float* __restrict__ in,
                                      __half* __restrict__ out,
                                      int K, int Ncols)
{
    __shared__ float tile[32][33];
    const int k0 = blockIdx.x * 32;
    const int n0 = blockIdx.y * 32;
    const int tx = threadIdx.x;
    const int ty = threadIdx.y;
#pragma unroll
    for (int i = 0; i < 32; i += 8) {
        int k = k0 + ty + i, n = n0 + tx;
        tile[ty + i][tx] = (k < K && n < Ncols) ? __ldg(in + (size_t)k * Ncols + n) : 0.f;
    }
    __syncthreads();
#pragma unroll
    for (int i = 0; i < 32; i += 8) {
        int n = n0 + ty + i, k = k0 + tx;
        if (n < Ncols && k < K)
            out[(size_t)n * K + k] = __float2half_rn(tile[tx][ty + i]);
    }
}

// ===========================================================================
// CSR build
// ===========================================================================
__global__ void hist_kernel(const int* __restrict__ dst, int* __restrict__ deg,
                            int n_edges)
{
    int e = blockIdx.x * blockDim.x + threadIdx.x;
    if (e < n_edges) atomicAdd(&deg[__ldg(dst + e)], 1);
}

__global__ void scan_kernel(const int* __restrict__ deg, int* __restrict__ indptr,
                            int n)
{
    const int T = 1024;
    __shared__ int sh[T];
    int t = threadIdx.x;
    int chunk = (n + T - 1) / T;
    int beg = t * chunk;
    int end = min(beg + chunk, n);
    int s = 0;
    for (int i = beg; i < end; i++) s += deg[i];
    sh[t] = s;
    __syncthreads();
    for (int off = 1; off < T; off <<= 1) {
        int v = sh[t];
        int u = (t >= off) ? sh[t - off] : 0;
        __syncthreads();
        sh[t] = v + u;
        __syncthreads();
    }
    int run = (t == 0) ? 0 : sh[t - 1];
    for (int i = beg; i < end; i++) { indptr[i] = run; run += deg[i]; }
    if (t == T - 1) indptr[n] = sh[T - 1];
}

__global__ void fill_kernel(const int* __restrict__ src, const int* __restrict__ dst,
                            const int* __restrict__ indptr, int* __restrict__ cursor,
                            int* __restrict__ csr, int n_edges)
{
    int e = blockIdx.x * blockDim.x + threadIdx.x;
    if (e >= n_edges) return;
    int d = __ldg(dst + e);
    int pos = __ldg(indptr + d) + atomicAdd(&cursor[d], 1);
    csr[pos] = __ldg(src + e);
}

// ===========================================================================
// Gather aggregation: 64 threads/node, LDG.128, 4-deep MLP unroll.
//   out[i] = rn( h[i] + sum_{j in N_in(i)} h[j] )
// ===========================================================================
__device__ __forceinline__ void add8(float* a, uint4 v)
{
    float2 g0 = __half22float2(*reinterpret_cast<__half2*>(&v.x));
    float2 g1 = __half22float2(*reinterpret_cast<__half2*>(&v.y));
    float2 g2 = __half22float2(*reinterpret_cast<__half2*>(&v.z));
    float2 g3 = __half22float2(*reinterpret_cast<__half2*>(&v.w));
    a[0] += g0.x; a[1] += g0.y; a[2] += g1.x; a[3] += g1.y;
    a[4] += g2.x; a[5] += g2.y; a[6] += g3.x; a[7] += g3.y;
}

__global__ __launch_bounds__(64)
void gather_agg_h(const uint4* __restrict__ h, const int* __restrict__ indptr,
                  const int* __restrict__ csr, uint4* __restrict__ out)
{
    __shared__ int nb[64];
    const int node = blockIdx.x;
    const int t = threadIdx.x;

    float a[8];
    add8(a, make_uint4(0, 0, 0, 0));
#pragma unroll
    for (int j = 0; j < 8; j++) a[j] = 0.f;
    add8(a, __ldg(h + (size_t)node * 64 + t));

    const int beg = __ldg(indptr + node);
    const int end = __ldg(indptr + node + 1);
    for (int base = beg; base < end; base += 64) {
        int cnt = min(64, end - base);
        if (t < cnt) nb[t] = __ldg(csr + base + t);
        __syncthreads();
        int i = 0;
        for (; i + 4 <= cnt; i += 4) {
            uint4 v0 = __ldg(h + (size_t)nb[i + 0] * 64 + t);
            uint4 v1 = __ldg(h + (size_t)nb[i + 1] * 64 + t);
            uint4 v2 = __ldg(h + (size_t)nb[i + 2] * 64 + t);
            uint4 v3 = __ldg(h + (size_t)nb[i + 3] * 64 + t);
            add8(a, v0); add8(a, v1); add8(a, v2); add8(a, v3);
        }
        for (; i < cnt; i++)
            add8(a, __ldg(h + (size_t)nb[i] * 64 + t));
        __syncthreads();
    }
    __half2 p0 = __floats2half2_rn(a[0], a[1]);
    __half2 p1 = __floats2half2_rn(a[2], a[3]);
    __half2 p2 = __floats2half2_rn(a[4], a[5]);
    __half2 p3 = __floats2half2_rn(a[6], a[7]);
    uint4 o;
    o.x = *reinterpret_cast<uint32_t*>(&p0);
    o.y = *reinterpret_cast<uint32_t*>(&p1);
    o.z = *reinterpret_cast<uint32_t*>(&p2);
    o.w = *reinterpret_cast<uint32_t*>(&p3);
    __stcs(out + (size_t)node * 64 + t, o);
}

// ===========================================================================
// fp16 mma.sync GEMM with ldmatrix fragment loads.
// 128 threads, 4 warps (2x2), 64x64 warp tiles, block 128x128, BK=64,
// cp.async 3-stage.  A half [M,512]; Bt half [N,512] (k-contig).
// ===========================================================================
#define HBK 64
#define HKT (KDIM / HBK)          // 8
#define HPITCH 72                 // halves per row (144B = 9 x 16B units)
#define HPB (HPITCH * 2)          // row pitch bytes
#define HAS_B (128 * HPB)         // 18432
#define HSTG  (2 * HAS_B)         // 36864
#define HSMEM (3 * HSTG)          // 110592

template<bool RELU, bool OUTH>
__global__ __launch_bounds__(128, 2)
void gin_hgemm(const __half* __restrict__ A, const __half* __restrict__ Bt,
               const float* __restrict__ bias, void* __restrict__ CoutV,
               int M, int N)
{
    extern __shared__ char smem[];
    const uint32_t sb = smem_to_u32(smem);

    const int tid  = threadIdx.x;
    const int wid  = tid >> 5;
    const int lane = tid & 31;
    const int wm   = wid & 1;
    const int wn   = wid >> 1;
    const int grp  = lane >> 2;
    const int tig  = lane & 3;

    const int m0 = blockIdx.x * BM;
    const int n0 = blockIdx.y * BN;

    float acc[4][8][4];
#pragma unroll
    for (int mi = 0; mi < 4; mi++)
#pragma unroll
        for (int ni = 0; ni < 8; ni++)
#pragma unroll
            for (int j = 0; j < 4; j++) acc[mi][ni][j] = 0.f;

    // ldmatrix per-thread base offsets (within a stage's A / B region)
    // A frag mi: rows r0+(lane&15), k-half selected by lane>>4
    const uint32_t aOff = (uint32_t)((wm * 64 + (lane & 15)) * HPB + (lane >> 4) * 16);
    // B frag pair p: n rows 16p+(lane&7)+8*(lane>>4), k-half by (lane>>3)&1
    const uint32_t bOff = (uint32_t)((wn * 64 + (lane & 7) + ((lane >> 4) & 1) * 8) * HPB
                                     + ((lane >> 3) & 1) * 16);

    auto issue = [&](int kt, int st) {
        const int kbase = kt * HBK;
        const uint32_t sA = sb + st * HSTG;
        const uint32_t sB = sA + HAS_B;
#pragma unroll
        for (int i = 0; i < 8; i++) {
            int idx = tid + i * 128;
            int row = idx >> 3;
            int u   = idx & 7;
            int gr  = m0 + row;
            bool ok = (gr < M);
            const __half* src = ok ? (A + (size_t)gr * KDIM + kbase + u * 8) : A;
            cp16(sA + row * HPB + u * 16, src, ok ? 16 : 0);
        }
#pragma unroll
        for (int i = 0; i < 8; i++) {
            int idx = tid + i * 128;
            int row = idx >> 3;
            int u   = idx & 7;
            int gn  = n0 + row;
            bool ok = (gn < N);
            const __half* src = ok ? (Bt + (size_t)gn * KDIM + kbase + u * 8) : Bt;
            cp16(sB + row * HPB + u * 16, src, ok ? 16 : 0);
        }
    };

    auto compute = [&](int st) {
        const uint32_t aBase = sb + st * HSTG + aOff;
        const uint32_t bBase = sb + st * HSTG + HAS_B + bOff;
#pragma unroll
        for (int s = 0; s < 4; s++) {
            const uint32_t ks = s * 32;           // 16 halves = 32B per k16 slice
            uint32_t af[4][4];
#pragma unroll
            for (int mi = 0; mi < 4; mi++)
                ldsm4(af[mi], aBase + mi * 16 * HPB + ks);
            uint32_t bf[4][4];
#pragma unroll
            for (int p = 0; p < 4; p++)
                ldsm4(bf[p], bBase + p * 16 * HPB + ks);
#pragma unroll
            for (int p = 0; p < 4; p++) {
#pragma unroll
                for (int mi = 0; mi < 4; mi++) {
                    mmaH(acc[mi][2 * p],     af[mi], bf[p][0], bf[p][1]);
                    mmaH(acc[mi][2 * p + 1], af[mi], bf[p][2], bf[p][3]);
                }
            }
        }
    };

    issue(0, 0); CP_COMMIT();
    issue(1, 1); CP_COMMIT();
    for (int kt = 0; kt < HKT; kt++) {
        CP_WAIT1();
        __syncthreads();
        const int nx = kt + 2;
        if (nx < HKT) issue(nx, nx % 3);
        CP_COMMIT();
        compute(kt % 3);
    }

    // ---- epilogue ----
#pragma unroll
    for (int nt = 0; nt < 8; nt++) {
        int col = n0 + wn * 64 + nt * 8 + tig * 2;
        if (col >= N) continue;
        float bv0 = __ldg(bias + col);
        float bv1 = __ldg(bias + col + 1);
#pragma unroll
        for (int mi = 0; mi < 4; mi++) {
            int rbase = m0 + wm * 64 + mi * 16 + grp;
#pragma unroll
            for (int h = 0; h < 2; h++) {
                int r = rbase + h * 8;
                if (r >= M) continue;
                float x0 = acc[mi][nt][h * 2 + 0] + bv0;
                float x1 = acc[mi][nt][h * 2 + 1] + bv1;
                if (RELU) { x0 = fmaxf(x0, 0.f); x1 = fmaxf(x1, 0.f); }
                if (OUTH) {
                    __half2 p = __floats2half2_rn(x0, x1);
                    *reinterpret_cast<__half2*>((__half*)CoutV + (size_t)r * N + col) = p;
                } else {
                    float2 o; o.x = x0; o.y = x1;
                    *reinterpret_cast<float2*>((float*)CoutV + (size_t)r * N + col) = o;
                }
            }
        }
    }
}

// ===========================================================================
// Launch
// ===========================================================================
extern "C" void kernel_launch(void* const* d_in, const int* in_sizes, int n_in,
                              void* d_out, int out_size)
{
    const float* feat = (const float*)d_in[0];
    const int*   src  = (const int*)d_in[1];
    const int*   dst  = (const int*)d_in[2];
    const float* W0   = (const float*)d_in[3];
    const float* b0   = (const float*)d_in[4];
    const float* W1   = (const float*)d_in[5];
    const float* b1   = (const float*)d_in[6];
    const float* W2   = (const float*)d_in[7];
    const float* b2   = (const float*)d_in[8];
    const float* Wc   = (const float*)d_in[9];
    const float* bc   = (const float*)d_in[10];

    const int n_nodes = in_sizes[0] / D;
    const int n_edges = in_sizes[1];
    const int n_cls   = in_sizes[10];

    __half *feath, *hh1, *hh2, *aggh, *wth;
    int *deg, *indptr, *cursor, *csr;
    cudaGetSymbolAddress((void**)&feath, g_feath);
    cudaGetSymbolAddress((void**)&hh1, g_hh1);
    cudaGetSymbolAddress((void**)&hh2, g_hh2);
    cudaGetSymbolAddress((void**)&aggh, g_aggh);
    cudaGetSymbolAddress((void**)&wth, g_wth);
    cudaGetSymbolAddress((void**)&deg, g_deg);
    cudaGetSymbolAddress((void**)&indptr, g_indptr);
    cudaGetSymbolAddress((void**)&cursor, g_cursor);
    cudaGetSymbolAddress((void**)&csr, g_csr);

    __half* W0t = wth;
    __half* W1t = wth + 262144;
    __half* W2t = wth + 524288;
    __half* Wct = wth + 786432;

    cudaFuncSetAttribute(gin_hgemm<true, true>,
                         cudaFuncAttributeMaxDynamicSharedMemorySize, HSMEM);
    cudaFuncSetAttribute(gin_hgemm<false, false>,
                         cudaFuncAttributeMaxDynamicSharedMemorySize, HSMEM);

    const int eBlocks = (n_edges + 255) / 256;

    // ---- setup: feat->fp16, weight transposes, CSR ----
    const int n8 = (n_nodes * D) / 8;
    feat2half_kernel<<<(n8 + 255) / 256, 256>>>((const float4*)feat,
                                                (uint4*)feath, n8);
    {
        dim3 tb(32, 8);
        dim3 tg(16, 16);
        transpose_half_kernel<<<tg, tb>>>(W0, W0t, KDIM, 512);
        transpose_half_kernel<<<tg, tb>>>(W1, W1t, KDIM, 512);
        transpose_half_kernel<<<tg, tb>>>(W2, W2t, KDIM, 512);
        dim3 tgc(16, (n_cls + 31) / 32);
        transpose_half_kernel<<<tgc, tb>>>(Wc, Wct, KDIM, n_cls);
    }
    cudaMemsetAsync(deg, 0, (size_t)n_nodes * sizeof(int));
    cudaMemsetAsync(cursor, 0, (size_t)n_nodes * sizeof(int));
    hist_kernel<<<eBlocks, 256>>>(dst, deg, n_edges);
    scan_kernel<<<1, 1024>>>(deg, indptr, n_nodes);
    fill_kernel<<<eBlocks, 256>>>(src, dst, indptr, cursor, csr, n_edges);

    dim3 gGrid((n_nodes + BM - 1) / BM, (D + BN - 1) / BN);
    dim3 cGrid((n_nodes + BM - 1) / BM, (n_cls + BN - 1) / BN);

    // Layer 0
    gather_agg_h<<<n_nodes, 64>>>((const uint4*)feath, indptr, csr, (uint4*)aggh);
    gin_hgemm<true, true><<<gGrid, 128, HSMEM>>>(aggh, W0t, b0, hh1, n_nodes, D);

    // Layer 1
    gather_agg_h<<<n_nodes, 64>>>((const uint4*)hh1, indptr, csr, (uint4*)aggh);
    gin_hgemm<true, true><<<gGrid, 128, HSMEM>>>(aggh, W1t, b1, hh2, n_nodes, D);

    // Layer 2
    gather_agg_h<<<n_nodes, 64>>>((const uint4*)hh2, indptr, csr, (uint4*)aggh);
    gin_hgemm<true, true><<<gGrid, 128, HSMEM>>>(aggh, W2t, b2, hh1, n_nodes, D);

    // Classifier (fp16 A, fp32 out)
    gin_hgemm<false, false><<<cGrid, 128, HSMEM>>>(hh1, Wct, bc, (float*)d_out,
                                                   n_nodes, n_cls);
}

// round 12
// speedup vs baseline: 5.9120x; 1.0297x over previous
#include <cuda_runtime.h>
#include <cuda_fp16.h>
#include <cstdint>

#define D 512
#define KDIM 512
#define BM 128

static const int MAX_NODES = 50000;
static const int MAX_EDGES = 400000;

__device__ __half g_feath[(size_t)MAX_NODES * D];
__device__ __half g_hh1[(size_t)MAX_NODES * D];
__device__ __half g_hh2[(size_t)MAX_NODES * D];
__device__ __half g_aggh[(size_t)MAX_NODES * D];
__device__ __half g_wth[3 * 512 * 512 + 64 * 512];   // transposed fp16 weights

__device__ int g_deg[MAX_NODES];
__device__ int g_indptr[MAX_NODES + 1];
__device__ int g_cursor[MAX_NODES];
__device__ int g_csr[MAX_EDGES];

// ===========================================================================
// helpers
// ===========================================================================
__device__ __forceinline__ uint32_t smem_to_u32(const void* p) {
    uint32_t a;
    asm("{ .reg .u64 t; cvta.to.shared.u64 t, %1; cvt.u32.u64 %0, t; }"
        : "=r"(a) : "l"(p));
    return a;
}

__device__ __forceinline__ void cp16(uint32_t dst, const void* src, int sz)
{
    asm volatile("cp.async.cg.shared.global [%0], [%1], 16, %2;"
                 :: "r"(dst), "l"(src), "r"(sz) : "memory");
}
#define CP_COMMIT() asm volatile("cp.async.commit_group;" ::: "memory")
#define CP_WAIT1()  asm volatile("cp.async.wait_group 1;" ::: "memory")

__device__ __forceinline__ void mmaH(float* c, const uint32_t* a, uint32_t b0, uint32_t b1)
{
    asm volatile(
        "mma.sync.aligned.m16n8k16.row.col.f32.f16.f16.f32 "
        "{%0,%1,%2,%3}, {%4,%5,%6,%7}, {%8,%9}, {%0,%1,%2,%3};\n"
        : "+f"(c[0]), "+f"(c[1]), "+f"(c[2]), "+f"(c[3])
        : "r"(a[0]), "r"(a[1]), "r"(a[2]), "r"(a[3]), "r"(b0), "r"(b1));
}

__device__ __forceinline__ void ldsm4(uint32_t* r, uint32_t addr)
{
    asm volatile(
        "ldmatrix.sync.aligned.m8n8.x4.shared.b16 {%0,%1,%2,%3}, [%4];"
        : "=r"(r[0]), "=r"(r[1]), "=r"(r[2]), "=r"(r[3]) : "r"(addr));
}

// ===========================================================================
// feat -> fp16
// ===========================================================================
__global__ void feat2half_kernel(const float4* __restrict__ in,
                                 uint4* __restrict__ out, int n8)
{
    int i = blockIdx.x * blockDim.x + threadIdx.x;
    if (i >= n8) return;
    float4 a = __ldg(in + i * 2);
    float4 b = __ldg(in + i * 2 + 1);
    __half2 p0 = __floats2half2_rn(a.x, a.y);
    __half2 p1 = __floats2half2_rn(a.z, a.w);
    __half2 p2 = __floats2half2_rn(b.x, b.y);
    __half2 p3 = __floats2half2_rn(b.z, b.w);
    uint4 o;
    o.x = *reinterpret_cast<uint32_t*>(&p0);
    o.y = *reinterpret_cast<uint32_t*>(&p1);
    o.z = *reinterpret_cast<uint32_t*>(&p2);
    o.w = *reinterpret_cast<uint32_t*>(&p3);
    out[i] = o;
}

// ===========================================================================
// batched weight transpose + fp16 for the 3 square 512x512 weights:
//   out_z[n][k] = (half)in_z[k][n]
// ===========================================================================
__global__ void transpose3_half_kernel(const float* __restrict__ in0,
                                       const float* __restrict__ in1,
                                       const float* __restrict__ in2,
                                       __half* __restrict__ out0,
                                       __half* __restrict__ out1,
                                       __half* __restrict__ out2)
{
    __shared__ float tile[32][33];
    const float* in  = (blockIdx.z == 0) ? in0 : (blockIdx.z == 1) ? in1 : in2;
    __half*     out  = (blockIdx.z == 0) ? out0 : (blockIdx.z == 1) ? out1 : out2;
    const int k0 = blockIdx.x * 32;
    const int n0 = blockIdx.y * 32;
    const int tx = threadIdx.x;
    const int ty = threadIdx.y;
#pragma unroll
    for (int i = 0; i < 32; i += 8) {
        tile[ty + i][tx] = __ldg(in + (size_t)(k0 + ty + i) * 512 + n0 + tx);
    }
    __syncthreads();
#pragma unroll
    for (int i = 0; i < 32; i += 8) {
        out[(size_t)(n0 + ty + i) * 512 + k0 + tx] = __float2half_rn(tile[tx][ty + i]);
    }
}

// general (classifier) transpose
__global__ void transpose_half_kernel(const float* __restrict__ in,
                                      __half* __restrict__ out,
                                      int K, int Ncols)
{
    __shared__ float tile[32][33];
    const int k0 = blockIdx.x * 32;
    const int n0 = blockIdx.y * 32;
    const int tx = threadIdx.x;
    const int ty = threadIdx.y;
#pragma unroll
    for (int i = 0; i < 32; i += 8) {
        int k = k0 + ty + i, n = n0 + tx;
        tile[ty + i][tx] = (k < K && n < Ncols) ? __ldg(in + (size_t)k * Ncols + n) : 0.f;
    }
    __syncthreads();
#pragma unroll
    for (int i = 0; i < 32; i += 8) {
        int n = n0 + ty + i, k = k0 + tx;
        if (n < Ncols && k < K)
            out[(size_t)n * K + k] = __float2half_rn(tile[tx][ty + i]);
    }
}

// ===========================================================================
// CSR build
// ===========================================================================
__global__ void hist_kernel(const int* __restrict__ dst, int* __restrict__ deg,
                            int n_edges)
{
    int e = blockIdx.x * blockDim.x + threadIdx.x;
    if (e < n_edges) atomicAdd(&deg[__ldg(dst + e)], 1);
}

__global__ void scan_kernel(const int* __restrict__ deg, int* __restrict__ indptr,
                            int n)
{
    const int T = 1024;
    __shared__ int sh[T];
    int t = threadIdx.x;
    int chunk = (n + T - 1) / T;
    int beg = t * chunk;
    int end = min(beg + chunk, n);
    int s = 0;
    for (int i = beg; i < end; i++) s += deg[i];
    sh[t] = s;
    __syncthreads();
    for (int off = 1; off < T; off <<= 1) {
        int v = sh[t];
        int u = (t >= off) ? sh[t - off] : 0;
        __syncthreads();
        sh[t] = v + u;
        __syncthreads();
    }
    int run = (t == 0) ? 0 : sh[t - 1];
    for (int i = beg; i < end; i++) { indptr[i] = run; run += deg[i]; }
    if (t == T - 1) indptr[n] = sh[T - 1];
}

__global__ void fill_kernel(const int* __restrict__ src, const int* __restrict__ dst,
                            const int* __restrict__ indptr, int* __restrict__ cursor,
                            int* __restrict__ csr, int n_edges)
{
    int e = blockIdx.x * blockDim.x + threadIdx.x;
    if (e >= n_edges) return;
    int d = __ldg(dst + e);
    int pos = __ldg(indptr + d) + atomicAdd(&cursor[d], 1);
    csr[pos] = __ldg(src + e);
}

// ===========================================================================
// Gather aggregation: 64 threads/node, LDG.128, 4-deep MLP unroll.
// ===========================================================================
__device__ __forceinline__ void add8(float* a, uint4 v)
{
    float2 g0 = __half22float2(*reinterpret_cast<__half2*>(&v.x));
    float2 g1 = __half22float2(*reinterpret_cast<__half2*>(&v.y));
    float2 g2 = __half22float2(*reinterpret_cast<__half2*>(&v.z));
    float2 g3 = __half22float2(*reinterpret_cast<__half2*>(&v.w));
    a[0] += g0.x; a[1] += g0.y; a[2] += g1.x; a[3] += g1.y;
    a[4] += g2.x; a[5] += g2.y; a[6] += g3.x; a[7] += g3.y;
}

__global__ __launch_bounds__(64)
void gather_agg_h(const uint4* __restrict__ h, const int* __restrict__ indptr,
                  const int* __restrict__ csr, uint4* __restrict__ out)
{
    __shared__ int nb[64];
    const int node = blockIdx.x;
    const int t = threadIdx.x;

    float a[8];
#pragma unroll
    for (int j = 0; j < 8; j++) a[j] = 0.f;
    add8(a, __ldg(h + (size_t)node * 64 + t));

    const int beg = __ldg(indptr + node);
    const int end = __ldg(indptr + node + 1);
    for (int base = beg; base < end; base += 64) {
        int cnt = min(64, end - base);
        if (t < cnt) nb[t] = __ldg(csr + base + t);
        __syncthreads();
        int i = 0;
        for (; i + 4 <= cnt; i += 4) {
            uint4 v0 = __ldg(h + (size_t)nb[i + 0] * 64 + t);
            uint4 v1 = __ldg(h + (size_t)nb[i + 1] * 64 + t);
            uint4 v2 = __ldg(h + (size_t)nb[i + 2] * 64 + t);
            uint4 v3 = __ldg(h + (size_t)nb[i + 3] * 64 + t);
            add8(a, v0); add8(a, v1); add8(a, v2); add8(a, v3);
        }
        for (; i < cnt; i++)
            add8(a, __ldg(h + (size_t)nb[i] * 64 + t));
        __syncthreads();
    }
    __half2 p0 = __floats2half2_rn(a[0], a[1]);
    __half2 p1 = __floats2half2_rn(a[2], a[3]);
    __half2 p2 = __floats2half2_rn(a[4], a[5]);
    __half2 p3 = __floats2half2_rn(a[6], a[7]);
    uint4 o;
    o.x = *reinterpret_cast<uint32_t*>(&p0);
    o.y = *reinterpret_cast<uint32_t*>(&p1);
    o.z = *reinterpret_cast<uint32_t*>(&p2);
    o.w = *reinterpret_cast<uint32_t*>(&p3);
    __stcs(out + (size_t)node * 64 + t, o);
}

// ===========================================================================
// fp16 mma.sync GEMM, templated warp grid 2 x WN (64x64 warp tiles).
// WN=2: 128 threads, BN=128 (hidden layers).  WN=1: 64 threads, BN=64
// (classifier).  BK=64, cp.async 3-stage, ldmatrix fragments.
// A half [M,512]; Bt half [N,512] (k-contig).  C = act(A @ Bt^T + bias).
// ===========================================================================
#define HBK 64
#define HKT (KDIM / HBK)          // 8
#define HPITCH 72                 // halves per row (144B = 9 x 16B units)
#define HPB (HPITCH * 2)          // row pitch bytes
#define HAS_B (128 * HPB)         // A stage: 18432 B

template<int WN, bool RELU, bool OUTH>
__global__ __launch_bounds__(64 * WN, 2)
void gin_hgemm(const __half* __restrict__ A, const __half* __restrict__ Bt,
               const float* __restrict__ bias, void* __restrict__ CoutV,
               int M, int N)
{
    constexpr int THREADS = 64 * WN;
    constexpr int BN      = 64 * WN;
    constexpr int BS_B    = BN * HPB;          // B stage bytes
    constexpr int STG     = HAS_B + BS_B;      // stage bytes

    extern __shared__ char smem[];
    const uint32_t sb = smem_to_u32(smem);

    const int tid  = threadIdx.x;
    const int wid  = tid >> 5;
    const int lane = tid & 31;
    const int wm   = wid & 1;
    const int wn   = wid >> 1;
    const int grp  = lane >> 2;
    const int tig  = lane & 3;

    const int m0 = blockIdx.x * BM;
    const int n0 = blockIdx.y * BN;

    float acc[4][8][4];
#pragma unroll
    for (int mi = 0; mi < 4; mi++)
#pragma unroll
        for (int ni = 0; ni < 8; ni++)
#pragma unroll
            for (int j = 0; j < 4; j++) acc[mi][ni][j] = 0.f;

    const uint32_t aOff = (uint32_t)((wm * 64 + (lane & 15)) * HPB + (lane >> 4) * 16);
    const uint32_t bOff = (uint32_t)((wn * 64 + (lane & 7) + ((lane >> 4) & 1) * 8) * HPB
                                     + ((lane >> 3) & 1) * 16);

    auto issue = [&](int kt, int st) {
        const int kbase = kt * HBK;
        const uint32_t sA = sb + st * STG;
        const uint32_t sB = sA + HAS_B;
#pragma unroll
        for (int i = 0; i < 1024 / THREADS; i++) {
            int idx = tid + i * THREADS;
            int row = idx >> 3;
            int u   = idx & 7;
            int gr  = m0 + row;
            bool ok = (gr < M);
            const __half* src = ok ? (A + (size_t)gr * KDIM + kbase + u * 8) : A;
            cp16(sA + row * HPB + u * 16, src, ok ? 16 : 0);
        }
#pragma unroll
        for (int i = 0; i < (BN * 8) / THREADS; i++) {
            int idx = tid + i * THREADS;
            int row = idx >> 3;
            int u   = idx & 7;
            int gn  = n0 + row;
            bool ok = (gn < N);
            const __half* src = ok ? (Bt + (size_t)gn * KDIM + kbase + u * 8) : Bt;
            cp16(sB + row * HPB + u * 16, src, ok ? 16 : 0);
        }
    };

    auto compute = [&](int st) {
        const uint32_t aBase = sb + st * STG + aOff;
        const uint32_t bBase = sb + st * STG + HAS_B + bOff;
#pragma unroll
        for (int s = 0; s < 4; s++) {
            const uint32_t ks = s * 32;
            uint32_t af[4][4];
#pragma unroll
            for (int mi = 0; mi < 4; mi++)
                ldsm4(af[mi], aBase + mi * 16 * HPB + ks);
            uint32_t bf[4][4];
#pragma unroll
            for (int p = 0; p < 4; p++)
                ldsm4(bf[p], bBase + p * 16 * HPB + ks);
#pragma unroll
            for (int p = 0; p < 4; p++) {
#pragma unroll
                for (int mi = 0; mi < 4; mi++) {
                    mmaH(acc[mi][2 * p],     af[mi], bf[p][0], bf[p][1]);
                    mmaH(acc[mi][2 * p + 1], af[mi], bf[p][2], bf[p][3]);
                }
            }
        }
    };

    issue(0, 0); CP_COMMIT();
    issue(1, 1); CP_COMMIT();
    for (int kt = 0; kt < HKT; kt++) {
        CP_WAIT1();
        __syncthreads();
        const int nx = kt + 2;
        if (nx < HKT) issue(nx, nx % 3);
        CP_COMMIT();
        compute(kt % 3);
    }

    // ---- epilogue ----
#pragma unroll
    for (int nt = 0; nt < 8; nt++) {
        int col = n0 + wn * 64 + nt * 8 + tig * 2;
        if (col >= N) continue;
        float bv0 = __ldg(bias + col);
        float bv1 = __ldg(bias + col + 1);
#pragma unroll
        for (int mi = 0; mi < 4; mi++) {
            int rbase = m0 + wm * 64 + mi * 16 + grp;
#pragma unroll
            for (int h = 0; h < 2; h++) {
                int r = rbase + h * 8;
                if (r >= M) continue;
                float x0 = acc[mi][nt][h * 2 + 0] + bv0;
                float x1 = acc[mi][nt][h * 2 + 1] + bv1;
                if (RELU) { x0 = fmaxf(x0, 0.f); x1 = fmaxf(x1, 0.f); }
                if (OUTH) {
                    __half2 p = __floats2half2_rn(x0, x1);
                    *reinterpret_cast<__half2*>((__half*)CoutV + (size_t)r * N + col) = p;
                } else {
                    float2 o; o.x = x0; o.y = x1;
                    *reinterpret_cast<float2*>((float*)CoutV + (size_t)r * N + col) = o;
                }
            }
        }
    }
}

#define HSMEM_L (3 * (HAS_B + 128 * HPB))      // WN=2 stages: 110592
#define HSMEM_C (3 * (HAS_B + 64 * HPB))       // WN=1 stages: 82944

// ===========================================================================
// Launch
// ===========================================================================
extern "C" void kernel_launch(void* const* d_in, const int* in_sizes, int n_in,
                              void* d_out, int out_size)
{
    const float* feat = (const float*)d_in[0];
    const int*   src  = (const int*)d_in[1];
    const int*   dst  = (const int*)d_in[2];
    const float* W0   = (const float*)d_in[3];
    const float* b0   = (const float*)d_in[4];
    const float* W1   = (const float*)d_in[5];
    const float* b1   = (const float*)d_in[6];
    const float* W2   = (const float*)d_in[7];
    const float* b2   = (const float*)d_in[8];
    const float* Wc   = (const float*)d_in[9];
    const float* bc   = (const float*)d_in[10];

    const int n_nodes = in_sizes[0] / D;
    const int n_edges = in_sizes[1];
    const int n_cls   = in_sizes[10];

    __half *feath, *hh1, *hh2, *aggh, *wth;
    int *deg, *indptr, *cursor, *csr;
    cudaGetSymbolAddress((void**)&feath, g_feath);
    cudaGetSymbolAddress((void**)&hh1, g_hh1);
    cudaGetSymbolAddress((void**)&hh2, g_hh2);
    cudaGetSymbolAddress((void**)&aggh, g_aggh);
    cudaGetSymbolAddress((void**)&wth, g_wth);
    cudaGetSymbolAddress((void**)&deg, g_deg);
    cudaGetSymbolAddress((void**)&indptr, g_indptr);
    cudaGetSymbolAddress((void**)&cursor, g_cursor);
    cudaGetSymbolAddress((void**)&csr, g_csr);

    __half* W0t = wth;
    __half* W1t = wth + 262144;
    __half* W2t = wth + 524288;
    __half* Wct = wth + 786432;

    cudaFuncSetAttribute(gin_hgemm<2, true, true>,
                         cudaFuncAttributeMaxDynamicSharedMemorySize, HSMEM_L);
    cudaFuncSetAttribute(gin_hgemm<1, false, false>,
                         cudaFuncAttributeMaxDynamicSharedMemorySize, HSMEM_C);

    const int eBlocks = (n_edges + 255) / 256;

    // ---- setup: feat->fp16, weight transposes, CSR ----
    const int n8 = (n_nodes * D) / 8;
    feat2half_kernel<<<(n8 + 255) / 256, 256>>>((const float4*)feat,
                                                (uint4*)feath, n8);
    {
        dim3 tb(32, 8);
        dim3 tg3(16, 16, 3);
        transpose3_half_kernel<<<tg3, tb>>>(W0, W1, W2, W0t, W1t, W2t);
        dim3 tgc(16, (n_cls + 31) / 32);
        transpose_half_kernel<<<tgc, tb>>>(Wc, Wct, KDIM, n_cls);
    }
    cudaMemsetAsync(deg, 0, (size_t)n_nodes * sizeof(int));
    cudaMemsetAsync(cursor, 0, (size_t)n_nodes * sizeof(int));
    hist_kernel<<<eBlocks, 256>>>(dst, deg, n_edges);
    scan_kernel<<<1, 1024>>>(deg, indptr, n_nodes);
    fill_kernel<<<eBlocks, 256>>>(src, dst, indptr, cursor, csr, n_edges);

    dim3 gGrid((n_nodes + BM - 1) / BM, 4);         // 512 / 128
    dim3 cGrid((n_nodes + BM - 1) / BM, 1);         // n_cls <= 64

    // Layer 0
    gather_agg_h<<<n_nodes, 64>>>((const uint4*)feath, indptr, csr, (uint4*)aggh);
    gin_hgemm<2, true, true><<<gGrid, 128, HSMEM_L>>>(aggh, W0t, b0, hh1, n_nodes, D);

    // Layer 1
    gather_agg_h<<<n_nodes, 64>>>((const uint4*)hh1, indptr, csr, (uint4*)aggh);
    gin_hgemm<2, true, true><<<gGrid, 128, HSMEM_L>>>(aggh, W1t, b1, hh2, n_nodes, D);

    // Layer 2
    gather_agg_h<<<n_nodes, 64>>>((const uint4*)hh2, indptr, csr, (uint4*)aggh);
    gin_hgemm<2, true, true><<<gGrid, 128, HSMEM_L>>>(aggh, W2t, b2, hh1, n_nodes, D);

    // Classifier (narrow-N variant: BN=64, 64 threads)
    gin_hgemm<1, false, false><<<cGrid, 64, HSMEM_C>>>(hh1, Wct, bc, (float*)d_out,
                                                       n_nodes, n_cls);
}

// round 13
// speedup vs baseline: 6.4012x; 1.0828x over previous
#include <cuda_runtime.h>
#include <cuda_fp16.h>
#include <cstdint>

#define D 512
#define KDIM 512
#define BM 128

static const int MAX_NODES = 50000;
static const int MAX_EDGES = 400000;

__device__ __half g_feath[(size_t)MAX_NODES * D];
__device__ __half g_hh1[(size_t)MAX_NODES * D];
__device__ __half g_hh2[(size_t)MAX_NODES * D];
__device__ __half g_aggh[(size_t)MAX_NODES * D];
__device__ __half g_wth[3 * 512 * 512 + 64 * 512];   // transposed fp16 weights

__device__ int g_deg[MAX_NODES];
__device__ int g_indptr[MAX_NODES + 1];
__device__ int g_cursor[MAX_NODES];
__device__ int g_csr[MAX_EDGES];

// ===========================================================================
// helpers
// ===========================================================================
__device__ __forceinline__ uint32_t smem_to_u32(const void* p) {
    uint32_t a;
    asm("{ .reg .u64 t; cvta.to.shared.u64 t, %1; cvt.u32.u64 %0, t; }"
        : "=r"(a) : "l"(p));
    return a;
}

__device__ __forceinline__ void cp16(uint32_t dst, const void* src, int sz)
{
    asm volatile("cp.async.cg.shared.global [%0], [%1], 16, %2;"
                 :: "r"(dst), "l"(src), "r"(sz) : "memory");
}
#define CP_COMMIT() asm volatile("cp.async.commit_group;" ::: "memory")
#define CP_WAIT0()  asm volatile("cp.async.wait_group 0;" ::: "memory")

__device__ __forceinline__ void mmaH(float* c, const uint32_t* a, uint32_t b0, uint32_t b1)
{
    asm volatile(
        "mma.sync.aligned.m16n8k16.row.col.f32.f16.f16.f32 "
        "{%0,%1,%2,%3}, {%4,%5,%6,%7}, {%8,%9}, {%0,%1,%2,%3};\n"
        : "+f"(c[0]), "+f"(c[1]), "+f"(c[2]), "+f"(c[3])
        : "r"(a[0]), "r"(a[1]), "r"(a[2]), "r"(a[3]), "r"(b0), "r"(b1));
}

__device__ __forceinline__ void ldsm4(uint32_t* r, uint32_t addr)
{
    asm volatile(
        "ldmatrix.sync.aligned.m8n8.x4.shared.b16 {%0,%1,%2,%3}, [%4];"
        : "=r"(r[0]), "=r"(r[1]), "=r"(r[2]), "=r"(r[3]) : "r"(addr));
}

// ===========================================================================
// feat -> fp16
// ===========================================================================
__global__ void feat2half_kernel(const float4* __restrict__ in,
                                 uint4* __restrict__ out, int n8)
{
    int i = blockIdx.x * blockDim.x + threadIdx.x;
    if (i >= n8) return;
    float4 a = __ldg(in + i * 2);
    float4 b = __ldg(in + i * 2 + 1);
    __half2 p0 = __floats2half2_rn(a.x, a.y);
    __half2 p1 = __floats2half2_rn(a.z, a.w);
    __half2 p2 = __floats2half2_rn(b.x, b.y);
    __half2 p3 = __floats2half2_rn(b.z, b.w);
    uint4 o;
    o.x = *reinterpret_cast<uint32_t*>(&p0);
    o.y = *reinterpret_cast<uint32_t*>(&p1);
    o.z = *reinterpret_cast<uint32_t*>(&p2);
    o.w = *reinterpret_cast<uint32_t*>(&p3);
    out[i] = o;
}

// ===========================================================================
// batched weight transpose + fp16 (3 x 512x512)
// ===========================================================================
__global__ void transpose3_half_kernel(const float* __restrict__ in0,
                                       const float* __restrict__ in1,
                                       const float* __restrict__ in2,
                                       __half* __restrict__ out0,
                                       __half* __restrict__ out1,
                                       __half* __restrict__ out2)
{
    __shared__ float tile[32][33];
    const float* in  = (blockIdx.z == 0) ? in0 : (blockIdx.z == 1) ? in1 : in2;
    __half*     out  = (blockIdx.z == 0) ? out0 : (blockIdx.z == 1) ? out1 : out2;
    const int k0 = blockIdx.x * 32;
    const int n0 = blockIdx.y * 32;
    const int tx = threadIdx.x;
    const int ty = threadIdx.y;
#pragma unroll
    for (int i = 0; i < 32; i += 8)
        tile[ty + i][tx] = __ldg(in + (size_t)(k0 + ty + i) * 512 + n0 + tx);
    __syncthreads();
#pragma unroll
    for (int i = 0; i < 32; i += 8)
        out[(size_t)(n0 + ty + i) * 512 + k0 + tx] = __float2half_rn(tile[tx][ty + i]);
}

__global__ void transpose_half_kernel(const float* __restrict__ in,
                                      __half* __restrict__ out,
                                      int K, int Ncols)
{
    __shared__ float tile[32][33];
    const int k0 = blockIdx.x * 32;
    const int n0 = blockIdx.y * 32;
    const int tx = threadIdx.x;
    const int ty = threadIdx.y;
#pragma unroll
    for (int i = 0; i < 32; i += 8) {
        int k = k0 + ty + i, n = n0 + tx;
        tile[ty + i][tx] = (k < K && n < Ncols) ? __ldg(in + (size_t)k * Ncols + n) : 0.f;
    }
    __syncthreads();
#pragma unroll
    for (int i = 0; i < 32; i += 8) {
        int n = n0 + ty + i, k = k0 + tx;
        if (n < Ncols && k < K)
            out[(size_t)n * K + k] = __float2half_rn(tile[tx][ty + i]);
    }
}

// ===========================================================================
// CSR build
// ===========================================================================
__global__ void hist_kernel(const int* __restrict__ dst, int* __restrict__ deg,
                            int n_edges)
{
    int e = blockIdx.x * blockDim.x + threadIdx.x;
    if (e < n_edges) atomicAdd(&deg[__ldg(dst + e)], 1);
}

__global__ void scan_kernel(const int* __restrict__ deg, int* __restrict__ indptr,
                            int n)
{
    const int T = 1024;
    __shared__ int sh[T];
    int t = threadIdx.x;
    int chunk = (n + T - 1) / T;
    int beg = t * chunk;
    int end = min(beg + chunk, n);
    int s = 0;
    for (int i = beg; i < end; i++) s += deg[i];
    sh[t] = s;
    __syncthreads();
    for (int off = 1; off < T; off <<= 1) {
        int v = sh[t];
        int u = (t >= off) ? sh[t - off] : 0;
        __syncthreads();
        sh[t] = v + u;
        __syncthreads();
    }
    int run = (t == 0) ? 0 : sh[t - 1];
    for (int i = beg; i < end; i++) { indptr[i] = run; run += deg[i]; }
    if (t == T - 1) indptr[n] = sh[T - 1];
}

__global__ void fill_kernel(const int* __restrict__ src, const int* __restrict__ dst,
                            const int* __restrict__ indptr, int* __restrict__ cursor,
                            int* __restrict__ csr, int n_edges)
{
    int e = blockIdx.x * blockDim.x + threadIdx.x;
    if (e >= n_edges) return;
    int d = __ldg(dst + e);
    int pos = __ldg(indptr + d) + atomicAdd(&cursor[d], 1);
    csr[pos] = __ldg(src + e);
}

// ===========================================================================
// Gather aggregation: 64 threads/node, LDG.128, 4-deep MLP unroll.
// ===========================================================================
__device__ __forceinline__ void add8(float* a, uint4 v)
{
    float2 g0 = __half22float2(*reinterpret_cast<__half2*>(&v.x));
    float2 g1 = __half22float2(*reinterpret_cast<__half2*>(&v.y));
    float2 g2 = __half22float2(*reinterpret_cast<__half2*>(&v.z));
    float2 g3 = __half22float2(*reinterpret_cast<__half2*>(&v.w));
    a[0] += g0.x; a[1] += g0.y; a[2] += g1.x; a[3] += g1.y;
    a[4] += g2.x; a[5] += g2.y; a[6] += g3.x; a[7] += g3.y;
}

__global__ __launch_bounds__(64)
void gather_agg_h(const uint4* __restrict__ h, const int* __restrict__ indptr,
                  const int* __restrict__ csr, uint4* __restrict__ out)
{
    __shared__ int nb[64];
    const int node = blockIdx.x;
    const int t = threadIdx.x;

    float a[8];
#pragma unroll
    for (int j = 0; j < 8; j++) a[j] = 0.f;
    add8(a, __ldg(h + (size_t)node * 64 + t));

    const int beg = __ldg(indptr + node);
    const int end = __ldg(indptr + node + 1);
    for (int base = beg; base < end; base += 64) {
        int cnt = min(64, end - base);
        if (t < cnt) nb[t] = __ldg(csr + base + t);
        __syncthreads();
        int i = 0;
        for (; i + 4 <= cnt; i += 4) {
            uint4 v0 = __ldg(h + (size_t)nb[i + 0] * 64 + t);
            uint4 v1 = __ldg(h + (size_t)nb[i + 1] * 64 + t);
            uint4 v2 = __ldg(h + (size_t)nb[i + 2] * 64 + t);
            uint4 v3 = __ldg(h + (size_t)nb[i + 3] * 64 + t);
            add8(a, v0); add8(a, v1); add8(a, v2); add8(a, v3);
        }
        for (; i < cnt; i++)
            add8(a, __ldg(h + (size_t)nb[i] * 64 + t));
        __syncthreads();
    }
    __half2 p0 = __floats2half2_rn(a[0], a[1]);
    __half2 p1 = __floats2half2_rn(a[2], a[3]);
    __half2 p2 = __floats2half2_rn(a[4], a[5]);
    __half2 p3 = __floats2half2_rn(a[6], a[7]);
    uint4 o;
    o.x = *reinterpret_cast<uint32_t*>(&p0);
    o.y = *reinterpret_cast<uint32_t*>(&p1);
    o.z = *reinterpret_cast<uint32_t*>(&p2);
    o.w = *reinterpret_cast<uint32_t*>(&p3);
    __stcs(out + (size_t)node * 64 + t, o);
}

// ===========================================================================
// fp16 mma.sync GEMM, 2-stage double buffer, 3 CTAs/SM target.
// Warp grid 2 x WN (64x64 warp tiles).  WN=2: BN=128 (layers).
// WN=1: BN=64 (classifier).  BK=64, ldmatrix fragments.
// ===========================================================================
#define HBK 64
#define HKT (KDIM / HBK)          // 8
#define HPITCH 72                 // halves per row (144B = 9 x 16B units)
#define HPB (HPITCH * 2)
#define HAS_B (128 * HPB)         // A stage: 18432 B

template<int WN, bool RELU, bool OUTH>
__global__ __launch_bounds__(64 * WN, 3)
void gin_hgemm(const __half* __restrict__ A, const __half* __restrict__ Bt,
               const float* __restrict__ bias, void* __restrict__ CoutV,
               int M, int N)
{
    constexpr int THREADS = 64 * WN;
    constexpr int BN      = 64 * WN;
    constexpr int BS_B    = BN * HPB;
    constexpr int STG     = HAS_B + BS_B;

    extern __shared__ char smem[];
    const uint32_t sb = smem_to_u32(smem);

    const int tid  = threadIdx.x;
    const int wid  = tid >> 5;
    const int lane = tid & 31;
    const int wm   = wid & 1;
    const int wn   = wid >> 1;
    const int grp  = lane >> 2;
    const int tig  = lane & 3;

    const int m0 = blockIdx.x * BM;
    const int n0 = blockIdx.y * BN;

    float acc[4][8][4];
#pragma unroll
    for (int mi = 0; mi < 4; mi++)
#pragma unroll
        for (int ni = 0; ni < 8; ni++)
#pragma unroll
            for (int j = 0; j < 4; j++) acc[mi][ni][j] = 0.f;

    const uint32_t aOff = (uint32_t)((wm * 64 + (lane & 15)) * HPB + (lane >> 4) * 16);
    const uint32_t bOff = (uint32_t)((wn * 64 + (lane & 7) + ((lane >> 4) & 1) * 8) * HPB
                                     + ((lane >> 3) & 1) * 16);

    auto issue = [&](int kt, int st) {
        const int kbase = kt * HBK;
        const uint32_t sA = sb + st * STG;
        const uint32_t sB = sA + HAS_B;
#pragma unroll
        for (int i = 0; i < 1024 / THREADS; i++) {
            int idx = tid + i * THREADS;
            int row = idx >> 3;
            int u   = idx & 7;
            int gr  = m0 + row;
            bool ok = (gr < M);
            const __half* src = ok ? (A + (size_t)gr * KDIM + kbase + u * 8) : A;
            cp16(sA + row * HPB + u * 16, src, ok ? 16 : 0);
        }
#pragma unroll
        for (int i = 0; i < (BN * 8) / THREADS; i++) {
            int idx = tid + i * THREADS;
            int row = idx >> 3;
            int u   = idx & 7;
            int gn  = n0 + row;
            bool ok = (gn < N);
            const __half* src = ok ? (Bt + (size_t)gn * KDIM + kbase + u * 8) : Bt;
            cp16(sB + row * HPB + u * 16, src, ok ? 16 : 0);
        }
    };

    // B fragments consumed immediately after each ldsm4 to minimize live regs
    auto compute = [&](int st) {
        const uint32_t aBase = sb + st * STG + aOff;
        const uint32_t bBase = sb + st * STG + HAS_B + bOff;
#pragma unroll
        for (int s = 0; s < 4; s++) {
            const uint32_t ks = s * 32;
            uint32_t af[4][4];
#pragma unroll
            for (int mi = 0; mi < 4; mi++)
                ldsm4(af[mi], aBase + mi * 16 * HPB + ks);
#pragma unroll
            for (int p = 0; p < 4; p++) {
                uint32_t bf[4];
                ldsm4(bf, bBase + p * 16 * HPB + ks);
#pragma unroll
                for (int mi = 0; mi < 4; mi++) {
                    mmaH(acc[mi][2 * p],     af[mi], bf[0], bf[1]);
                    mmaH(acc[mi][2 * p + 1], af[mi], bf[2], bf[3]);
                }
            }
        }
    };

    // 2-stage double buffer: load(kt+1) overlaps compute(kt)
    issue(0, 0); CP_COMMIT();
    for (int kt = 0; kt < HKT; kt++) {
        CP_WAIT0();
        __syncthreads();
        const int nx = kt + 1;
        if (nx < HKT) { issue(nx, nx & 1); CP_COMMIT(); }
        compute(kt & 1);
    }

    // ---- epilogue ----
#pragma unroll
    for (int nt = 0; nt < 8; nt++) {
        int col = n0 + wn * 64 + nt * 8 + tig * 2;
        if (col >= N) continue;
        float bv0 = __ldg(bias + col);
        float bv1 = __ldg(bias + col + 1);
#pragma unroll
        for (int mi = 0; mi < 4; mi++) {
            int rbase = m0 + wm * 64 + mi * 16 + grp;
#pragma unroll
            for (int h = 0; h < 2; h++) {
                int r = rbase + h * 8;
                if (r >= M) continue;
                float x0 = acc[mi][nt][h * 2 + 0] + bv0;
                float x1 = acc[mi][nt][h * 2 + 1] + bv1;
                if (RELU) { x0 = fmaxf(x0, 0.f); x1 = fmaxf(x1, 0.f); }
                if (OUTH) {
                    __half2 p = __floats2half2_rn(x0, x1);
                    *reinterpret_cast<__half2*>((__half*)CoutV + (size_t)r * N + col) = p;
                } else {
                    float2 o; o.x = x0; o.y = x1;
                    *reinterpret_cast<float2*>((float*)CoutV + (size_t)r * N + col) = o;
                }
            }
        }
    }
}

#define HSMEM_L (2 * (HAS_B + 128 * HPB))      // 73728
#define HSMEM_C (2 * (HAS_B + 64 * HPB))       // 55296

// ===========================================================================
// Launch
// ===========================================================================
extern "C" void kernel_launch(void* const* d_in, const int* in_sizes, int n_in,
                              void* d_out, int out_size)
{
    const float* feat = (const float*)d_in[0];
    const int*   src  = (const int*)d_in[1];
    const int*   dst  = (const int*)d_in[2];
    const float* W0   = (const float*)d_in[3];
    const float* b0   = (const float*)d_in[4];
    const float* W1   = (const float*)d_in[5];
    const float* b1   = (const float*)d_in[6];
    const float* W2   = (const float*)d_in[7];
    const float* b2   = (const float*)d_in[8];
    const float* Wc   = (const float*)d_in[9];
    const float* bc   = (const float*)d_in[10];

    const int n_nodes = in_sizes[0] / D;
    const int n_edges = in_sizes[1];
    const int n_cls   = in_sizes[10];

    __half *feath, *hh1, *hh2, *aggh, *wth;
    int *deg, *indptr, *cursor, *csr;
    cudaGetSymbolAddress((void**)&feath, g_feath);
    cudaGetSymbolAddress((void**)&hh1, g_hh1);
    cudaGetSymbolAddress((void**)&hh2, g_hh2);
    cudaGetSymbolAddress((void**)&aggh, g_aggh);
    cudaGetSymbolAddress((void**)&wth, g_wth);
    cudaGetSymbolAddress((void**)&deg, g_deg);
    cudaGetSymbolAddress((void**)&indptr, g_indptr);
    cudaGetSymbolAddress((void**)&cursor, g_cursor);
    cudaGetSymbolAddress((void**)&csr, g_csr);

    __half* W0t = wth;
    __half* W1t = wth + 262144;
    __half* W2t = wth + 524288;
    __half* Wct = wth + 786432;

    cudaFuncSetAttribute(gin_hgemm<2, true, true>,
                         cudaFuncAttributeMaxDynamicSharedMemorySize, HSMEM_L);
    cudaFuncSetAttribute(gin_hgemm<1, false, false>,
                         cudaFuncAttributeMaxDynamicSharedMemorySize, HSMEM_C);

    const int eBlocks = (n_edges + 255) / 256;

    // ---- setup: feat->fp16, weight transposes, CSR ----
    const int n8 = (n_nodes * D) / 8;
    feat2half_kernel<<<(n8 + 255) / 256, 256>>>((const float4*)feat,
                                                (uint4*)feath, n8);
    {
        dim3 tb(32, 8);
        dim3 tg3(16, 16, 3);
        transpose3_half_kernel<<<tg3, tb>>>(W0, W1, W2, W0t, W1t, W2t);
        dim3 tgc(16, (n_cls + 31) / 32);
        transpose_half_kernel<<<tgc, tb>>>(Wc, Wct, KDIM, n_cls);
    }
    cudaMemsetAsync(deg, 0, (size_t)n_nodes * sizeof(int));
    cudaMemsetAsync(cursor, 0, (size_t)n_nodes * sizeof(int));
    hist_kernel<<<eBlocks, 256>>>(dst, deg, n_edges);
    scan_kernel<<<1, 1024>>>(deg, indptr, n_nodes);
    fill_kernel<<<eBlocks, 256>>>(src, dst, indptr, cursor, csr, n_edges);

    dim3 gGrid((n_nodes + BM - 1) / BM, 4);
    dim3 cGrid((n_nodes + BM - 1) / BM, 1);

    // Layer 0
    gather_agg_h<<<n_nodes, 64>>>((const uint4*)feath, indptr, csr, (uint4*)aggh);
    gin_hgemm<2, true, true><<<gGrid, 128, HSMEM_L>>>(aggh, W0t, b0, hh1, n_nodes, D);

    // Layer 1
    gather_agg_h<<<n_nodes, 64>>>((const uint4*)hh1, indptr, csr, (uint4*)aggh);
    gin_hgemm<2, true, true><<<gGrid, 128, HSMEM_L>>>(aggh, W1t, b1, hh2, n_nodes, D);

    // Layer 2
    gather_agg_h<<<n_nodes, 64>>>((const uint4*)hh2, indptr, csr, (uint4*)aggh);
    gin_hgemm<2, true, true><<<gGrid, 128, HSMEM_L>>>(aggh, W2t, b2, hh1, n_nodes, D);

    // Classifier
    gin_hgemm<1, false, false><<<cGrid, 64, HSMEM_C>>>(hh1, Wct, bc, (float*)d_out,
                                                       n_nodes, n_cls);
}